// round 5
// baseline (speedup 1.0000x reference)
#include <cuda_runtime.h>
#include <cuda_bf16.h>
#include <math.h>
#include <stdint.h>

// ============================================================================
// GCN decoder chain. Big GEMMs on tensor cores via mma.sync m16n8k16 bf16 with
// 2-term splitting (C = Ahi*Bhi + Ahi*Blo + Alo*Bhi). Round 5: MMA issue order
// grouped by split term -> dependent MMAs on the same accumulator are 16
// instructions apart instead of back-to-back (HMMA RAW-chain fix).
// cp.async double-buffered mainloop, ldmatrix fragment loads, SYRK mirroring.
// NOTE: tcgen05 is unavailable — harness ptxas targets sm_103 (no 'a').
// ============================================================================

#define NROWS 10000
#define ADJ_N 100000000LL
#define SSTR 40                       // smem k-stride (bf16), conflict-free
#define ARR_BYTES (128 * SSTR * 2)    // 10240 per operand array
#define STAGE_BYTES (4 * ARR_BYTES)   // 40960 per stage (AH, AL, BH, BL)
#define SMEM_BYTES (2 * STAGE_BYTES)  // 81920 (also >= 128*132*4 mirror tile)

// ---------------- scratch (static __device__, allocation-free) -------------
__device__ __nv_bfloat16 g_adj_hi[100000000];
__device__ __nv_bfloat16 g_adj_lo[100000000];
__device__ __nv_bfloat16 g_bt_hi[500 * 10000];
__device__ __nv_bfloat16 g_bt_lo[500 * 10000];
__device__ __nv_bfloat16 g_zh_hi[10000 * 512];   // pads (cols 500..511) stay 0
__device__ __nv_bfloat16 g_zh_lo[10000 * 512];
__device__ float g_f1[10000 * 512];
__device__ float g_f2[10000 * 512];

// ---------------- helpers ----------------------------------------------------
__device__ __forceinline__ void split2(float x, __nv_bfloat16& h, __nv_bfloat16& l) {
    h = __float2bfloat16(x);
    l = __float2bfloat16(x - __bfloat162float(h));
}

__device__ __forceinline__ void cp16(uint32_t daddr, const void* src, int ok) {
    int sz = ok ? 16 : 0;
    asm volatile("cp.async.cg.shared.global [%0], [%1], 16, %2;"
                 :: "r"(daddr), "l"(src), "r"(sz));
}
__device__ __forceinline__ void cp_commit() {
    asm volatile("cp.async.commit_group;");
}
__device__ __forceinline__ void cp_wait1() {
    asm volatile("cp.async.wait_group 1;");
}
__device__ __forceinline__ void ldsm4(uint32_t& r0, uint32_t& r1, uint32_t& r2,
                                      uint32_t& r3, uint32_t addr) {
    asm volatile("ldmatrix.sync.aligned.m8n8.x4.shared.b16 {%0,%1,%2,%3}, [%4];"
                 : "=r"(r0), "=r"(r1), "=r"(r2), "=r"(r3) : "r"(addr));
}
__device__ __forceinline__ void mma16816(float c[4], const uint32_t a[4],
                                         const uint32_t b[2]) {
    asm volatile(
        "mma.sync.aligned.m16n8k16.row.col.f32.bf16.bf16.f32 "
        "{%0,%1,%2,%3}, {%4,%5,%6,%7}, {%8,%9}, {%0,%1,%2,%3};"
        : "+f"(c[0]), "+f"(c[1]), "+f"(c[2]), "+f"(c[3])
        : "r"(a[0]), "r"(a[1]), "r"(a[2]), "r"(a[3]), "r"(b[0]), "r"(b[1]));
}

// ---------------- adj split (elementwise, float4) ---------------------------
__global__ void split_vec4(const float* __restrict__ x,
                           __nv_bfloat16* __restrict__ hi,
                           __nv_bfloat16* __restrict__ lo, int n4)
{
    int i = blockIdx.x * blockDim.x + threadIdx.x;
    if (i >= n4) return;
    float4 v = reinterpret_cast<const float4*>(x)[i];
    __nv_bfloat16 h0, h1, h2, h3, l0, l1, l2, l3;
    split2(v.x, h0, l0); split2(v.y, h1, l1);
    split2(v.z, h2, l2); split2(v.w, h3, l3);
    reinterpret_cast<__nv_bfloat162*>(hi)[2 * i + 0] = __halves2bfloat162(h0, h1);
    reinterpret_cast<__nv_bfloat162*>(hi)[2 * i + 1] = __halves2bfloat162(h2, h3);
    reinterpret_cast<__nv_bfloat162*>(lo)[2 * i + 0] = __halves2bfloat162(l0, l1);
    reinterpret_cast<__nv_bfloat162*>(lo)[2 * i + 1] = __halves2bfloat162(l2, l3);
}

// ---------------- transpose + split: T[Kt,Nn] fp32 -> hi/lo [Nn,Kt] bf16 ----
__global__ void tsplit_kernel(const float* __restrict__ T, int Kt, int Nn,
                              __nv_bfloat16* __restrict__ hi,
                              __nv_bfloat16* __restrict__ lo)
{
    __shared__ float sm[32][33];
    int tx = threadIdx.x & 31;
    int ty = threadIdx.x >> 5;
    int k0 = blockIdx.y * 32;
    int n0 = blockIdx.x * 32;
    #pragma unroll
    for (int r = 0; r < 4; r++) {
        int row = k0 + ty + r * 8;
        int col = n0 + tx;
        sm[ty + r * 8][tx] = (row < Kt && col < Nn) ? T[(size_t)row * Nn + col] : 0.0f;
    }
    __syncthreads();
    #pragma unroll
    for (int r = 0; r < 4; r++) {
        int n = n0 + ty + r * 8;
        int k = k0 + tx;
        if (n < Nn && k < Kt) {
            float v = sm[tx][ty + r * 8];
            __nv_bfloat16 h, l;
            split2(v, h, l);
            hi[(size_t)n * Kt + k] = h;
            lo[(size_t)n * Kt + k] = l;
        }
    }
}

// ---------------- tensor-core split-bf16 GEMM -------------------------------
// C[M,N] = A[M,K] @ B[N,K]^T. ACT: 0 none, 1 tanh, 2 sigmoid.
// WSPLIT: also write bf16 split of C. MIRROR: triangular grid + symmetric
// mirror store (requires M == N, A == B semantics).
template <int ACT, int WSPLIT, int MIRROR>
__global__ __launch_bounds__(256, 1) void mma_gemm(
    const __nv_bfloat16* __restrict__ Ahi, const __nv_bfloat16* __restrict__ Alo, int lda,
    const __nv_bfloat16* __restrict__ Bhi, const __nv_bfloat16* __restrict__ Blo, int ldb,
    float* __restrict__ C, int ldc,
    __nv_bfloat16* __restrict__ Shi, __nv_bfloat16* __restrict__ Slo, int lds,
    int M, int N, int K)
{
    extern __shared__ char smem[];

    const int t    = threadIdx.x;
    const int lane = t & 31;
    const int wid  = t >> 5;
    const int wm   = (wid >> 2) * 64;
    const int wn   = (wid & 3) * 32;
    const int g    = lane >> 2;
    const int tg   = lane & 3;

    int bx, by;
    if (MIRROR) {
        int bid = blockIdx.x;
        by = (int)((sqrtf(8.0f * (float)bid + 1.0f) - 1.0f) * 0.5f);
        while ((by + 1) * (by + 2) / 2 <= bid) by++;
        while (by * (by + 1) / 2 > bid) by--;
        bx = bid - by * (by + 1) / 2;
    } else {
        bx = blockIdx.x;
        by = blockIdx.y;
    }
    const int m0 = by * 128;
    const int n0 = bx * 128;

    float acc[4][4][4];
    #pragma unroll
    for (int i = 0; i < 4; i++)
        #pragma unroll
        for (int j = 0; j < 4; j++)
            #pragma unroll
            for (int c = 0; c < 4; c++) acc[i][j][c] = 0.0f;

    // loader indices: 256 threads * 2 iters -> (row 0..127, chunk 0..3)
    const int lr0 = t >> 2;
    const int lc0 = (t & 3) * 8;

    // ldmatrix lane addressing
    const int a_row = lane & 15;              // row within 16-row frag
    const int a_c8  = (lane >> 4) * 8;        // k offset 0/8
    const int b_row = (lane & 7) + ((lane >> 4) << 3);
    const int b_c8  = ((lane >> 3) & 1) * 8;

    const int ntiles = (K + 31) / 32;

    // ---- stage loader (cp.async) ----
    auto load_stage = [&](int s, int k0) {
        char* sb = smem + s * STAGE_BYTES;
        #pragma unroll
        for (int it = 0; it < 2; it++) {
            int r   = lr0 + it * 64;
            int c8  = lc0;
            int gk  = k0 + c8;
            int kok = (gk < K);
            int ga  = m0 + r;
            int aok = kok && (ga < M);
            int gb  = n0 + r;
            int bok = kok && (gb < N);
            size_t aoff = aok ? ((size_t)ga * lda + gk) : 0;
            size_t boff = bok ? ((size_t)gb * ldb + gk) : 0;
            uint32_t so = (uint32_t)(r * SSTR + c8) * 2;
            uint32_t base = (uint32_t)__cvta_generic_to_shared(sb);
            cp16(base + 0 * ARR_BYTES + so, Ahi + aoff, aok);
            cp16(base + 1 * ARR_BYTES + so, Alo + aoff, aok);
            cp16(base + 2 * ARR_BYTES + so, Bhi + boff, bok);
            cp16(base + 3 * ARR_BYTES + so, Blo + boff, bok);
        }
    };

    load_stage(0, 0);
    cp_commit();

    int s = 0;
    for (int kt = 0; kt < ntiles; kt++) {
        __syncthreads();                  // stage s^1 consumers from prev iter done
        load_stage(s ^ 1, (kt + 1) * 32); // zero-fills / preds handle the tail
        cp_commit();
        cp_wait1();                       // stage s data landed
        __syncthreads();

        const char* sb = smem + s * STAGE_BYTES;
        const __nv_bfloat16* sAH = (const __nv_bfloat16*)(sb);
        const __nv_bfloat16* sAL = (const __nv_bfloat16*)(sb + ARR_BYTES);
        const __nv_bfloat16* sBH = (const __nv_bfloat16*)(sb + 2 * ARR_BYTES);
        const __nv_bfloat16* sBL = (const __nv_bfloat16*)(sb + 3 * ARR_BYTES);

        #pragma unroll
        for (int ks = 0; ks < 32; ks += 16) {
            uint32_t ah[4][4], al[4][4], bh[2][4], bl[2][4];
            #pragma unroll
            for (int i = 0; i < 4; i++) {
                int off = (wm + i * 16 + a_row) * SSTR + ks + a_c8;
                ldsm4(ah[i][0], ah[i][1], ah[i][2], ah[i][3],
                      (uint32_t)__cvta_generic_to_shared(sAH + off));
                ldsm4(al[i][0], al[i][1], al[i][2], al[i][3],
                      (uint32_t)__cvta_generic_to_shared(sAL + off));
            }
            #pragma unroll
            for (int jp = 0; jp < 2; jp++) {
                int off = (wn + jp * 16 + b_row) * SSTR + ks + b_c8;
                ldsm4(bh[jp][0], bh[jp][1], bh[jp][2], bh[jp][3],
                      (uint32_t)__cvta_generic_to_shared(sBH + off));
                ldsm4(bl[jp][0], bl[jp][1], bl[jp][2], bl[jp][3],
                      (uint32_t)__cvta_generic_to_shared(sBL + off));
            }
            // Term-major issue order: all 16 MMAs of a split term are
            // independent (distinct accumulators); RAW reuse of acc[i][j]
            // is 16 instructions apart -> HMMA pipe stays fed.
            #pragma unroll
            for (int i = 0; i < 4; i++)
                #pragma unroll
                for (int j = 0; j < 4; j++)
                    mma16816(acc[i][j], ah[i], &bh[j >> 1][(j & 1) * 2]);
            #pragma unroll
            for (int i = 0; i < 4; i++)
                #pragma unroll
                for (int j = 0; j < 4; j++)
                    mma16816(acc[i][j], ah[i], &bl[j >> 1][(j & 1) * 2]);
            #pragma unroll
            for (int i = 0; i < 4; i++)
                #pragma unroll
                for (int j = 0; j < 4; j++)
                    mma16816(acc[i][j], al[i], &bh[j >> 1][(j & 1) * 2]);
        }
        s ^= 1;
    }

    const bool do_mirror = MIRROR && (bx != by);
    float* tile = (float*)smem;       // 128 x 132 fp32, aliases stage buffers
    if (do_mirror) __syncthreads();   // mainloop smem reads done before overwrite

    // ---- epilogue ----
    #pragma unroll
    for (int i = 0; i < 4; i++) {
        #pragma unroll
        for (int j = 0; j < 4; j++) {
            int nl = wn + j * 8 + 2 * tg;
            int cn = n0 + nl;
            if (cn >= N) continue;
            #pragma unroll
            for (int h = 0; h < 2; h++) {
                int ml = wm + i * 16 + g + h * 8;
                int rm = m0 + ml;
                if (rm >= M) continue;
                float v0 = acc[i][j][2 * h + 0];
                float v1 = acc[i][j][2 * h + 1];
                if (ACT == 1) { v0 = tanhf(v0); v1 = tanhf(v1); }
                else if (ACT == 2) {
                    v0 = 1.0f / (1.0f + expf(-v0));
                    v1 = 1.0f / (1.0f + expf(-v1));
                }
                C[(size_t)rm * ldc + cn]     = v0;
                C[(size_t)rm * ldc + cn + 1] = v1;
                if (do_mirror) {
                    tile[(nl + 0) * 132 + ml] = v0;
                    tile[(nl + 1) * 132 + ml] = v1;
                }
                if (WSPLIT) {
                    __nv_bfloat16 hh, ll;
                    split2(v0, hh, ll);
                    Shi[(size_t)rm * lds + cn] = hh;
                    Slo[(size_t)rm * lds + cn] = ll;
                    split2(v1, hh, ll);
                    Shi[(size_t)rm * lds + cn + 1] = hh;
                    Slo[(size_t)rm * lds + cn + 1] = ll;
                }
            }
        }
    }

    if (do_mirror) {
        __syncthreads();
        // write block (bx,by): C[n0+r][m0+c] = tile[r][c], coalesced
        for (int i = t; i < 128 * 32; i += 256) {
            int r  = i >> 5;
            int c4 = (i & 31) * 4;
            int gr = n0 + r;
            int gc = m0 + c4;
            if (gr < N && gc < M) {
                float4 v = *reinterpret_cast<const float4*>(&tile[r * 132 + c4]);
                *reinterpret_cast<float4*>(&C[(size_t)gr * ldc + gc]) = v;
            }
        }
    }
}

// ---------------- small fp32 SIMT GEMM (NN, no act) for X @ W ---------------
#define BM 128
#define BN 128
#define BK 8
__global__ __launch_bounds__(256) void simt_gemm(
    const float* __restrict__ A, const float* __restrict__ B,
    float* __restrict__ C, int M, int N, int K)
{
    __shared__ float As[BK][BM];
    __shared__ float Bs[BK][BN];
    const int t  = threadIdx.x;
    const int m0 = blockIdx.y * BM;
    const int n0 = blockIdx.x * BN;
    const int ar = t >> 1, ac = (t & 1) * 4;
    const int br = t >> 5, bc = (t & 31) * 4;
    const int ty = t >> 4, tx = t & 15;

    float acc[8][8];
    #pragma unroll
    for (int i = 0; i < 8; i++)
        #pragma unroll
        for (int j = 0; j < 8; j++) acc[i][j] = 0.0f;

    for (int k0 = 0; k0 < K; k0 += BK) {
        float4 av = make_float4(0.f, 0.f, 0.f, 0.f);
        if (m0 + ar < M && k0 + ac < K)
            av = *reinterpret_cast<const float4*>(A + (size_t)(m0 + ar) * K + k0 + ac);
        As[ac + 0][ar] = av.x; As[ac + 1][ar] = av.y;
        As[ac + 2][ar] = av.z; As[ac + 3][ar] = av.w;
        float4 bv = make_float4(0.f, 0.f, 0.f, 0.f);
        if (k0 + br < K && n0 + bc < N)
            bv = *reinterpret_cast<const float4*>(B + (size_t)(k0 + br) * N + n0 + bc);
        *reinterpret_cast<float4*>(&Bs[br][bc]) = bv;
        __syncthreads();
        #pragma unroll
        for (int kk = 0; kk < BK; kk++) {
            float a[8], b[8];
            *reinterpret_cast<float4*>(&a[0]) = *reinterpret_cast<const float4*>(&As[kk][ty * 8]);
            *reinterpret_cast<float4*>(&a[4]) = *reinterpret_cast<const float4*>(&As[kk][ty * 8 + 4]);
            *reinterpret_cast<float4*>(&b[0]) = *reinterpret_cast<const float4*>(&Bs[kk][tx * 8]);
            *reinterpret_cast<float4*>(&b[4]) = *reinterpret_cast<const float4*>(&Bs[kk][tx * 8 + 4]);
            #pragma unroll
            for (int i = 0; i < 8; i++)
                #pragma unroll
                for (int j = 0; j < 8; j++)
                    acc[i][j] = fmaf(a[i], b[j], acc[i][j]);
        }
        __syncthreads();
    }
    #pragma unroll
    for (int i = 0; i < 8; i++) {
        int m = m0 + ty * 8 + i;
        if (m >= M) continue;
        #pragma unroll
        for (int j = 0; j < 8; j++) {
            int n = n0 + tx * 8 + j;
            if (n < N) C[(size_t)m * N + n] = acc[i][j];
        }
    }
}

// ---------------- driver -----------------------------------------------------
extern "C" void kernel_launch(void* const* d_in, const int* in_sizes, int n_in,
                              void* d_out, int out_size)
{
    const float* z_igae = (const float*)d_in[0];  // [10000, 20]
    const float* adj    = (const float*)d_in[1];  // [10000, 10000]
    const float* w3     = (const float*)d_in[2];  // [20, 256]
    const float* w4     = (const float*)d_in[3];  // [256, 128]
    const float* w5     = (const float*)d_in[4];  // [128, 500]

    float* out      = (float*)d_out;
    float* z_hat    = out;                          // [10000, 500]
    float* z_hatadj = out + (size_t)NROWS * 500;    // [10000, 10000]

    __nv_bfloat16 *adjH, *adjL, *btH, *btL, *zhH, *zhL;
    float *f1, *f2;
    cudaGetSymbolAddress((void**)&adjH, g_adj_hi);
    cudaGetSymbolAddress((void**)&adjL, g_adj_lo);
    cudaGetSymbolAddress((void**)&btH,  g_bt_hi);
    cudaGetSymbolAddress((void**)&btL,  g_bt_lo);
    cudaGetSymbolAddress((void**)&zhH,  g_zh_hi);
    cudaGetSymbolAddress((void**)&zhL,  g_zh_lo);
    cudaGetSymbolAddress((void**)&f1,   g_f1);
    cudaGetSymbolAddress((void**)&f2,   g_f2);

    cudaFuncSetAttribute(mma_gemm<1, 0, 0>,
                         cudaFuncAttributeMaxDynamicSharedMemorySize, SMEM_BYTES);
    cudaFuncSetAttribute(mma_gemm<0, 1, 0>,
                         cudaFuncAttributeMaxDynamicSharedMemorySize, SMEM_BYTES);
    cudaFuncSetAttribute(mma_gemm<2, 0, 1>,
                         cudaFuncAttributeMaxDynamicSharedMemorySize, SMEM_BYTES);

    // 0. split adj -> bf16 hi/lo
    {
        int n4 = (int)(ADJ_N / 4);
        split_vec4<<<(n4 + 255) / 256, 256>>>(adj, adjH, adjL, n4);
    }

    dim3 blk(256);

    // 1. T1 = z_igae @ w3  [10000,256]
    simt_gemm<<<dim3(2, 79), blk>>>(z_igae, w3, f1, NROWS, 256, 20);
    // 2. transpose+split T1 -> [256,10000]
    tsplit_kernel<<<dim3(8, 313), blk>>>(f1, NROWS, 256, btH, btL);
    // 3. Z1 = tanh(adj @ T1)  [10000,256]
    mma_gemm<1, 0, 0><<<dim3(2, 79), blk, SMEM_BYTES>>>(
        adjH, adjL, NROWS, btH, btL, NROWS,
        f2, 256, nullptr, nullptr, 0, NROWS, 256, NROWS);
    // 4. T2 = Z1 @ w4  [10000,128]
    simt_gemm<<<dim3(1, 79), blk>>>(f2, w4, f1, NROWS, 128, 256);
    // 5. transpose+split T2 -> [128,10000]
    tsplit_kernel<<<dim3(4, 313), blk>>>(f1, NROWS, 128, btH, btL);
    // 6. Z2 = tanh(adj @ T2)  [10000,128]
    mma_gemm<1, 0, 0><<<dim3(1, 79), blk, SMEM_BYTES>>>(
        adjH, adjL, NROWS, btH, btL, NROWS,
        f2, 128, nullptr, nullptr, 0, NROWS, 128, NROWS);
    // 7. T3 = Z2 @ w5  [10000,500]
    simt_gemm<<<dim3(4, 79), blk>>>(f2, w5, f1, NROWS, 500, 128);
    // 8. transpose+split T3 -> [500,10000]
    tsplit_kernel<<<dim3(16, 313), blk>>>(f1, NROWS, 500, btH, btL);
    // 9. z_hat = adj @ T3  [10000,500], fused bf16 split (lds=512, pads stay 0)
    mma_gemm<0, 1, 0><<<dim3(4, 79), blk, SMEM_BYTES>>>(
        adjH, adjL, NROWS, btH, btL, NROWS,
        z_hat, 500, zhH, zhL, 512, NROWS, 500, NROWS);
    // 10. z_hat_adj = sigmoid(z_hat @ z_hat^T): symmetric -> triangular grid
    {
        int nblk = 79 * 80 / 2;  // 3160
        mma_gemm<2, 0, 1><<<dim3(nblk), blk, SMEM_BYTES>>>(
            zhH, zhL, 512, zhH, zhL, 512,
            z_hatadj, NROWS, nullptr, nullptr, 0, NROWS, NROWS, 512);
    }
}

// round 6
// speedup vs baseline: 1.4162x; 1.4162x over previous
#include <cuda_runtime.h>
#include <cuda_bf16.h>
#include <math.h>
#include <stdint.h>

// ============================================================================
// GCN decoder chain. Tensor-core GEMMs via mma.sync m16n8k16 bf16.
// Round 6: adj-GEMMs use 2-term split  C = adj_bf16 @ (Bhi + Blo)
//   (adj > 0, unbiased rounding, K=10000 -> adj-rounding error ~4e-5; the
//    Alo term is statistically unnecessary). Smaller smem + fewer regs ->
//   __launch_bounds__(256,2) = 2 CTAs/SM for latency hiding.
// Syrk (z_hat @ z_hat^T, K=500, mixed sign) keeps full 3-term split.
// NOTE: tcgen05 unavailable — harness ptxas targets sm_103 (no 'a').
// ============================================================================

#define NROWS 10000
#define ADJ_N 100000000LL
#define SSTR 40                       // smem k-stride (bf16), conflict-free
#define ARR_BYTES (128 * SSTR * 2)    // 10240 per operand array
#define SMEM3 (2 * 3 * ARR_BYTES)     // 61440: 2 stages x {A, BH, BL}
#define SMEM4 (2 * 4 * ARR_BYTES)     // 81920: 2 stages x {AH, AL, BH, BL}

// ---------------- scratch (static __device__, allocation-free) -------------
__device__ __nv_bfloat16 g_adj_hi[100000000];
__device__ __nv_bfloat16 g_bt_hi[500 * 10000];
__device__ __nv_bfloat16 g_bt_lo[500 * 10000];
__device__ __nv_bfloat16 g_zh_hi[10000 * 512];   // pads (cols 500..511) stay 0
__device__ __nv_bfloat16 g_zh_lo[10000 * 512];
__device__ float g_f1[10000 * 512];
__device__ float g_f2[10000 * 512];

// ---------------- helpers ----------------------------------------------------
__device__ __forceinline__ void split2(float x, __nv_bfloat16& h, __nv_bfloat16& l) {
    h = __float2bfloat16(x);
    l = __float2bfloat16(x - __bfloat162float(h));
}

__device__ __forceinline__ void cp16(uint32_t daddr, const void* src, int ok) {
    int sz = ok ? 16 : 0;
    asm volatile("cp.async.cg.shared.global [%0], [%1], 16, %2;"
                 :: "r"(daddr), "l"(src), "r"(sz));
}
__device__ __forceinline__ void cp_commit() {
    asm volatile("cp.async.commit_group;");
}
__device__ __forceinline__ void cp_wait1() {
    asm volatile("cp.async.wait_group 1;");
}
__device__ __forceinline__ void ldsm4(uint32_t& r0, uint32_t& r1, uint32_t& r2,
                                      uint32_t& r3, uint32_t addr) {
    asm volatile("ldmatrix.sync.aligned.m8n8.x4.shared.b16 {%0,%1,%2,%3}, [%4];"
                 : "=r"(r0), "=r"(r1), "=r"(r2), "=r"(r3) : "r"(addr));
}
__device__ __forceinline__ void mma16816(float c[4], const uint32_t a[4],
                                         const uint32_t b[2]) {
    asm volatile(
        "mma.sync.aligned.m16n8k16.row.col.f32.bf16.bf16.f32 "
        "{%0,%1,%2,%3}, {%4,%5,%6,%7}, {%8,%9}, {%0,%1,%2,%3};"
        : "+f"(c[0]), "+f"(c[1]), "+f"(c[2]), "+f"(c[3])
        : "r"(a[0]), "r"(a[1]), "r"(a[2]), "r"(a[3]), "r"(b[0]), "r"(b[1]));
}

// ---------------- adj -> bf16 (hi only), float4 -----------------------------
__global__ void conv_vec4(const float* __restrict__ x,
                          __nv_bfloat16* __restrict__ hi, int n4)
{
    int i = blockIdx.x * blockDim.x + threadIdx.x;
    if (i >= n4) return;
    float4 v = reinterpret_cast<const float4*>(x)[i];
    reinterpret_cast<__nv_bfloat162*>(hi)[2 * i + 0] =
        __halves2bfloat162(__float2bfloat16(v.x), __float2bfloat16(v.y));
    reinterpret_cast<__nv_bfloat162*>(hi)[2 * i + 1] =
        __halves2bfloat162(__float2bfloat16(v.z), __float2bfloat16(v.w));
}

// ---------------- transpose + split: T[Kt,Nn] fp32 -> hi/lo [Nn,Kt] bf16 ----
__global__ void tsplit_kernel(const float* __restrict__ T, int Kt, int Nn,
                              __nv_bfloat16* __restrict__ hi,
                              __nv_bfloat16* __restrict__ lo)
{
    __shared__ float sm[32][33];
    int tx = threadIdx.x & 31;
    int ty = threadIdx.x >> 5;
    int k0 = blockIdx.y * 32;
    int n0 = blockIdx.x * 32;
    #pragma unroll
    for (int r = 0; r < 4; r++) {
        int row = k0 + ty + r * 8;
        int col = n0 + tx;
        sm[ty + r * 8][tx] = (row < Kt && col < Nn) ? T[(size_t)row * Nn + col] : 0.0f;
    }
    __syncthreads();
    #pragma unroll
    for (int r = 0; r < 4; r++) {
        int n = n0 + ty + r * 8;
        int k = k0 + tx;
        if (n < Nn && k < Kt) {
            float v = sm[tx][ty + r * 8];
            __nv_bfloat16 h, l;
            split2(v, h, l);
            hi[(size_t)n * Kt + k] = h;
            lo[(size_t)n * Kt + k] = l;
        }
    }
}

// ---------------- tensor-core split-bf16 GEMM -------------------------------
// C[M,N] = A[M,K] @ B[N,K]^T. ACT: 0 none, 1 tanh, 2 sigmoid.
// WSPLIT: also write bf16 split of C. MIRROR: triangular grid + mirror store.
// ASPLIT: 1 -> 3-term (AH*BH + AH*BL + AL*BH); 0 -> 2-term (A*BH + A*BL),
//         A given as single bf16 array (Alo unused), smaller smem, 2 CTAs/SM.
template <int ACT, int WSPLIT, int MIRROR, int ASPLIT>
__global__ __launch_bounds__(256, ASPLIT ? 1 : 2) void mma_gemm(
    const __nv_bfloat16* __restrict__ Ahi, const __nv_bfloat16* __restrict__ Alo, int lda,
    const __nv_bfloat16* __restrict__ Bhi, const __nv_bfloat16* __restrict__ Blo, int ldb,
    float* __restrict__ C, int ldc,
    __nv_bfloat16* __restrict__ Shi, __nv_bfloat16* __restrict__ Slo, int lds,
    int M, int N, int K)
{
    extern __shared__ char smem[];
    constexpr int NARR = ASPLIT ? 4 : 3;
    constexpr int STAGE = NARR * ARR_BYTES;

    const int t    = threadIdx.x;
    const int lane = t & 31;
    const int wid  = t >> 5;
    const int wm   = (wid >> 2) * 64;
    const int wn   = (wid & 3) * 32;
    const int g    = lane >> 2;
    const int tg   = lane & 3;

    int bx, by;
    if (MIRROR) {
        int bid = blockIdx.x;
        by = (int)((sqrtf(8.0f * (float)bid + 1.0f) - 1.0f) * 0.5f);
        while ((by + 1) * (by + 2) / 2 <= bid) by++;
        while (by * (by + 1) / 2 > bid) by--;
        bx = bid - by * (by + 1) / 2;
    } else {
        bx = blockIdx.x;
        by = blockIdx.y;
    }
    const int m0 = by * 128;
    const int n0 = bx * 128;

    float acc[4][4][4];
    #pragma unroll
    for (int i = 0; i < 4; i++)
        #pragma unroll
        for (int j = 0; j < 4; j++)
            #pragma unroll
            for (int c = 0; c < 4; c++) acc[i][j][c] = 0.0f;

    // ldmatrix lane addressing
    const int a_row = lane & 15;
    const int a_c8  = (lane >> 4) * 8;
    const int b_row = (lane & 7) + ((lane >> 4) << 3);
    const int b_c8  = ((lane >> 3) & 1) * 8;

    const int ntiles = (K + 31) / 32;

    // ---- stage loader (cp.async): NARR arrays x 512 16B-chunks ----
    auto load_stage = [&](int s, int k0) {
        uint32_t base = (uint32_t)__cvta_generic_to_shared(smem) + s * STAGE;
        #pragma unroll
        for (int it = 0; it < 2 * NARR; it++) {
            int idx = t + it * 256;
            int arr = idx >> 9;             // 0..NARR-1
            int rem = idx & 511;
            int r   = rem >> 2;             // 0..127
            int c8  = (rem & 3) * 8;
            int gk  = k0 + c8;
            int kok = (gk < K);
            const __nv_bfloat16* src;
            int ok;
            if (ASPLIT) {
                if (arr < 2) {
                    int ga = m0 + r;
                    ok  = kok && (ga < M);
                    src = (arr == 0 ? Ahi : Alo) + (ok ? ((size_t)ga * lda + gk) : 0);
                } else {
                    int gb = n0 + r;
                    ok  = kok && (gb < N);
                    src = (arr == 2 ? Bhi : Blo) + (ok ? ((size_t)gb * ldb + gk) : 0);
                }
            } else {
                if (arr == 0) {
                    int ga = m0 + r;
                    ok  = kok && (ga < M);
                    src = Ahi + (ok ? ((size_t)ga * lda + gk) : 0);
                } else {
                    int gb = n0 + r;
                    ok  = kok && (gb < N);
                    src = (arr == 1 ? Bhi : Blo) + (ok ? ((size_t)gb * ldb + gk) : 0);
                }
            }
            uint32_t so = (uint32_t)(r * SSTR + c8) * 2;
            cp16(base + (uint32_t)arr * ARR_BYTES + so, src, ok);
        }
    };

    load_stage(0, 0);
    cp_commit();

    int s = 0;
    for (int kt = 0; kt < ntiles; kt++) {
        __syncthreads();
        load_stage(s ^ 1, (kt + 1) * 32);
        cp_commit();
        cp_wait1();
        __syncthreads();

        const char* sb = smem + s * STAGE;
        const __nv_bfloat16* sAH = (const __nv_bfloat16*)(sb);
        const __nv_bfloat16* sAL = (const __nv_bfloat16*)(sb + ARR_BYTES);  // ASPLIT only
        const __nv_bfloat16* sBH = (const __nv_bfloat16*)(sb + (NARR - 2) * ARR_BYTES);
        const __nv_bfloat16* sBL = (const __nv_bfloat16*)(sb + (NARR - 1) * ARR_BYTES);

        #pragma unroll
        for (int ks = 0; ks < 32; ks += 16) {
            uint32_t ah[4][4], al[4][4], bh[2][4], bl[2][4];
            #pragma unroll
            for (int i = 0; i < 4; i++) {
                int off = (wm + i * 16 + a_row) * SSTR + ks + a_c8;
                ldsm4(ah[i][0], ah[i][1], ah[i][2], ah[i][3],
                      (uint32_t)__cvta_generic_to_shared(sAH + off));
                if (ASPLIT)
                    ldsm4(al[i][0], al[i][1], al[i][2], al[i][3],
                          (uint32_t)__cvta_generic_to_shared(sAL + off));
            }
            #pragma unroll
            for (int jp = 0; jp < 2; jp++) {
                int off = (wn + jp * 16 + b_row) * SSTR + ks + b_c8;
                ldsm4(bh[jp][0], bh[jp][1], bh[jp][2], bh[jp][3],
                      (uint32_t)__cvta_generic_to_shared(sBH + off));
                ldsm4(bl[jp][0], bl[jp][1], bl[jp][2], bl[jp][3],
                      (uint32_t)__cvta_generic_to_shared(sBL + off));
            }
            #pragma unroll
            for (int i = 0; i < 4; i++)
                #pragma unroll
                for (int j = 0; j < 4; j++)
                    mma16816(acc[i][j], ah[i], &bh[j >> 1][(j & 1) * 2]);
            #pragma unroll
            for (int i = 0; i < 4; i++)
                #pragma unroll
                for (int j = 0; j < 4; j++)
                    mma16816(acc[i][j], ah[i], &bl[j >> 1][(j & 1) * 2]);
            if (ASPLIT) {
                #pragma unroll
                for (int i = 0; i < 4; i++)
                    #pragma unroll
                    for (int j = 0; j < 4; j++)
                        mma16816(acc[i][j], al[i], &bh[j >> 1][(j & 1) * 2]);
            }
        }
        s ^= 1;
    }

    const bool do_mirror = MIRROR && (bx != by);
    float* tile = (float*)smem;       // 128 x 132 fp32 (fits in SMEM4 path)
    if (do_mirror) __syncthreads();

    // ---- epilogue ----
    #pragma unroll
    for (int i = 0; i < 4; i++) {
        #pragma unroll
        for (int j = 0; j < 4; j++) {
            int nl = wn + j * 8 + 2 * tg;
            int cn = n0 + nl;
            if (cn >= N) continue;
            #pragma unroll
            for (int h = 0; h < 2; h++) {
                int ml = wm + i * 16 + g + h * 8;
                int rm = m0 + ml;
                if (rm >= M) continue;
                float v0 = acc[i][j][2 * h + 0];
                float v1 = acc[i][j][2 * h + 1];
                if (ACT == 1) { v0 = tanhf(v0); v1 = tanhf(v1); }
                else if (ACT == 2) {
                    v0 = 1.0f / (1.0f + expf(-v0));
                    v1 = 1.0f / (1.0f + expf(-v1));
                }
                C[(size_t)rm * ldc + cn]     = v0;
                C[(size_t)rm * ldc + cn + 1] = v1;
                if (do_mirror) {
                    tile[(nl + 0) * 132 + ml] = v0;
                    tile[(nl + 1) * 132 + ml] = v1;
                }
                if (WSPLIT) {
                    __nv_bfloat16 hh, ll;
                    split2(v0, hh, ll);
                    Shi[(size_t)rm * lds + cn] = hh;
                    Slo[(size_t)rm * lds + cn] = ll;
                    split2(v1, hh, ll);
                    Shi[(size_t)rm * lds + cn + 1] = hh;
                    Slo[(size_t)rm * lds + cn + 1] = ll;
                }
            }
        }
    }

    if (do_mirror) {
        __syncthreads();
        for (int i = t; i < 128 * 32; i += 256) {
            int r  = i >> 5;
            int c4 = (i & 31) * 4;
            int gr = n0 + r;
            int gc = m0 + c4;
            if (gr < N && gc < M) {
                float4 v = *reinterpret_cast<const float4*>(&tile[r * 132 + c4]);
                *reinterpret_cast<float4*>(&C[(size_t)gr * ldc + gc]) = v;
            }
        }
    }
}

// ---------------- small fp32 SIMT GEMM (NN, no act) for X @ W ---------------
#define BM 128
#define BN 128
#define BK 8
__global__ __launch_bounds__(256) void simt_gemm(
    const float* __restrict__ A, const float* __restrict__ B,
    float* __restrict__ C, int M, int N, int K)
{
    __shared__ float As[BK][BM];
    __shared__ float Bs[BK][BN];
    const int t  = threadIdx.x;
    const int m0 = blockIdx.y * BM;
    const int n0 = blockIdx.x * BN;
    const int ar = t >> 1, ac = (t & 1) * 4;
    const int br = t >> 5, bc = (t & 31) * 4;
    const int ty = t >> 4, tx = t & 15;

    float acc[8][8];
    #pragma unroll
    for (int i = 0; i < 8; i++)
        #pragma unroll
        for (int j = 0; j < 8; j++) acc[i][j] = 0.0f;

    for (int k0 = 0; k0 < K; k0 += BK) {
        float4 av = make_float4(0.f, 0.f, 0.f, 0.f);
        if (m0 + ar < M && k0 + ac < K)
            av = *reinterpret_cast<const float4*>(A + (size_t)(m0 + ar) * K + k0 + ac);
        As[ac + 0][ar] = av.x; As[ac + 1][ar] = av.y;
        As[ac + 2][ar] = av.z; As[ac + 3][ar] = av.w;
        float4 bv = make_float4(0.f, 0.f, 0.f, 0.f);
        if (k0 + br < K && n0 + bc < N)
            bv = *reinterpret_cast<const float4*>(B + (size_t)(k0 + br) * N + n0 + bc);
        *reinterpret_cast<float4*>(&Bs[br][bc]) = bv;
        __syncthreads();
        #pragma unroll
        for (int kk = 0; kk < BK; kk++) {
            float a[8], b[8];
            *reinterpret_cast<float4*>(&a[0]) = *reinterpret_cast<const float4*>(&As[kk][ty * 8]);
            *reinterpret_cast<float4*>(&a[4]) = *reinterpret_cast<const float4*>(&As[kk][ty * 8 + 4]);
            *reinterpret_cast<float4*>(&b[0]) = *reinterpret_cast<const float4*>(&Bs[kk][tx * 8]);
            *reinterpret_cast<float4*>(&b[4]) = *reinterpret_cast<const float4*>(&Bs[kk][tx * 8 + 4]);
            #pragma unroll
            for (int i = 0; i < 8; i++)
                #pragma unroll
                for (int j = 0; j < 8; j++)
                    acc[i][j] = fmaf(a[i], b[j], acc[i][j]);
        }
        __syncthreads();
    }
    #pragma unroll
    for (int i = 0; i < 8; i++) {
        int m = m0 + ty * 8 + i;
        if (m >= M) continue;
        #pragma unroll
        for (int j = 0; j < 8; j++) {
            int n = n0 + tx * 8 + j;
            if (n < N) C[(size_t)m * N + n] = acc[i][j];
        }
    }
}

// ---------------- driver -----------------------------------------------------
extern "C" void kernel_launch(void* const* d_in, const int* in_sizes, int n_in,
                              void* d_out, int out_size)
{
    const float* z_igae = (const float*)d_in[0];  // [10000, 20]
    const float* adj    = (const float*)d_in[1];  // [10000, 10000]
    const float* w3     = (const float*)d_in[2];  // [20, 256]
    const float* w4     = (const float*)d_in[3];  // [256, 128]
    const float* w5     = (const float*)d_in[4];  // [128, 500]

    float* out      = (float*)d_out;
    float* z_hat    = out;                          // [10000, 500]
    float* z_hatadj = out + (size_t)NROWS * 500;    // [10000, 10000]

    __nv_bfloat16 *adjH, *btH, *btL, *zhH, *zhL;
    float *f1, *f2;
    cudaGetSymbolAddress((void**)&adjH, g_adj_hi);
    cudaGetSymbolAddress((void**)&btH,  g_bt_hi);
    cudaGetSymbolAddress((void**)&btL,  g_bt_lo);
    cudaGetSymbolAddress((void**)&zhH,  g_zh_hi);
    cudaGetSymbolAddress((void**)&zhL,  g_zh_lo);
    cudaGetSymbolAddress((void**)&f1,   g_f1);
    cudaGetSymbolAddress((void**)&f2,   g_f2);

    cudaFuncSetAttribute(mma_gemm<1, 0, 0, 0>,
                         cudaFuncAttributeMaxDynamicSharedMemorySize, SMEM3);
    cudaFuncSetAttribute(mma_gemm<0, 1, 0, 0>,
                         cudaFuncAttributeMaxDynamicSharedMemorySize, SMEM3);
    cudaFuncSetAttribute(mma_gemm<2, 0, 1, 1>,
                         cudaFuncAttributeMaxDynamicSharedMemorySize, SMEM4);

    // 0. adj -> bf16 (hi only)
    {
        int n4 = (int)(ADJ_N / 4);
        conv_vec4<<<(n4 + 255) / 256, 256>>>(adj, adjH, n4);
    }

    dim3 blk(256);

    // 1. T1 = z_igae @ w3  [10000,256]
    simt_gemm<<<dim3(2, 79), blk>>>(z_igae, w3, f1, NROWS, 256, 20);
    // 2. transpose+split T1 -> [256,10000]
    tsplit_kernel<<<dim3(8, 313), blk>>>(f1, NROWS, 256, btH, btL);
    // 3. Z1 = tanh(adj @ T1)  [10000,256], 2-term
    mma_gemm<1, 0, 0, 0><<<dim3(2, 79), blk, SMEM3>>>(
        adjH, nullptr, NROWS, btH, btL, NROWS,
        f2, 256, nullptr, nullptr, 0, NROWS, 256, NROWS);
    // 4. T2 = Z1 @ w4  [10000,128]
    simt_gemm<<<dim3(1, 79), blk>>>(f2, w4, f1, NROWS, 128, 256);
    // 5. transpose+split T2 -> [128,10000]
    tsplit_kernel<<<dim3(4, 313), blk>>>(f1, NROWS, 128, btH, btL);
    // 6. Z2 = tanh(adj @ T2)  [10000,128], 2-term
    mma_gemm<1, 0, 0, 0><<<dim3(1, 79), blk, SMEM3>>>(
        adjH, nullptr, NROWS, btH, btL, NROWS,
        f2, 128, nullptr, nullptr, 0, NROWS, 128, NROWS);
    // 7. T3 = Z2 @ w5  [10000,500]
    simt_gemm<<<dim3(4, 79), blk>>>(f2, w5, f1, NROWS, 500, 128);
    // 8. transpose+split T3 -> [500,10000]
    tsplit_kernel<<<dim3(16, 313), blk>>>(f1, NROWS, 500, btH, btL);
    // 9. z_hat = adj @ T3  [10000,500], 2-term, fused bf16 split (lds=512)
    mma_gemm<0, 1, 0, 0><<<dim3(4, 79), blk, SMEM3>>>(
        adjH, nullptr, NROWS, btH, btL, NROWS,
        z_hat, 500, zhH, zhL, 512, NROWS, 500, NROWS);
    // 10. z_hat_adj = sigmoid(z_hat @ z_hat^T): 3-term, triangular + mirror
    {
        int nblk = 79 * 80 / 2;  // 3160
        mma_gemm<2, 0, 1, 1><<<dim3(nblk), blk, SMEM4>>>(
            zhH, zhL, 512, zhH, zhL, 512,
            z_hatadj, NROWS, nullptr, nullptr, 0, NROWS, NROWS, 512);
    }
}

// round 7
// speedup vs baseline: 1.5560x; 1.0987x over previous
#include <cuda_runtime.h>
#include <cuda_bf16.h>
#include <math.h>
#include <stdint.h>

// ============================================================================
// GCN decoder chain. Tensor-core GEMMs via mma.sync m16n8k16 bf16.
// Round 7: split-K (blockIdx.z) for the grid-starved adj-GEMMs (layers 1-2)
//   + fused reduce+tanh pass. Layer-2 previously ran 79 CTAs on 148 SMs.
// adj-GEMMs: 2-term split  C = adj_bf16 @ (Bhi + Blo)  (adj > 0, K=10000).
// Syrk keeps full 3-term split; triangular grid + mirror.
// NOTE: tcgen05 unavailable — harness ptxas targets sm_103 (no 'a').
// ============================================================================

#define NROWS 10000
#define ADJ_N 100000000LL
#define SSTR 40                       // smem k-stride (bf16), conflict-free
#define ARR_BYTES (128 * SSTR * 2)    // 10240 per operand array
#define SMEM3 (2 * 3 * ARR_BYTES)     // 61440: 2 stages x {A, BH, BL}
#define SMEM4 (2 * 4 * ARR_BYTES)     // 81920: 2 stages x {AH, AL, BH, BL}

// ---------------- scratch (static __device__, allocation-free) -------------
__device__ __nv_bfloat16 g_adj_hi[100000000];
__device__ __nv_bfloat16 g_bt_hi[500 * 10000];
__device__ __nv_bfloat16 g_bt_lo[500 * 10000];
__device__ __nv_bfloat16 g_zh_hi[10000 * 512];   // pads (cols 500..511) stay 0
__device__ __nv_bfloat16 g_zh_lo[10000 * 512];
__device__ float g_f1[10000 * 512];
__device__ float g_f2[10000 * 512];

// ---------------- helpers ----------------------------------------------------
__device__ __forceinline__ void split2(float x, __nv_bfloat16& h, __nv_bfloat16& l) {
    h = __float2bfloat16(x);
    l = __float2bfloat16(x - __bfloat162float(h));
}

__device__ __forceinline__ void cp16(uint32_t daddr, const void* src, int ok) {
    int sz = ok ? 16 : 0;
    asm volatile("cp.async.cg.shared.global [%0], [%1], 16, %2;"
                 :: "r"(daddr), "l"(src), "r"(sz));
}
__device__ __forceinline__ void cp_commit() {
    asm volatile("cp.async.commit_group;");
}
__device__ __forceinline__ void cp_wait1() {
    asm volatile("cp.async.wait_group 1;");
}
__device__ __forceinline__ void ldsm4(uint32_t& r0, uint32_t& r1, uint32_t& r2,
                                      uint32_t& r3, uint32_t addr) {
    asm volatile("ldmatrix.sync.aligned.m8n8.x4.shared.b16 {%0,%1,%2,%3}, [%4];"
                 : "=r"(r0), "=r"(r1), "=r"(r2), "=r"(r3) : "r"(addr));
}
__device__ __forceinline__ void mma16816(float c[4], const uint32_t a[4],
                                         const uint32_t b[2]) {
    asm volatile(
        "mma.sync.aligned.m16n8k16.row.col.f32.bf16.bf16.f32 "
        "{%0,%1,%2,%3}, {%4,%5,%6,%7}, {%8,%9}, {%0,%1,%2,%3};"
        : "+f"(c[0]), "+f"(c[1]), "+f"(c[2]), "+f"(c[3])
        : "r"(a[0]), "r"(a[1]), "r"(a[2]), "r"(a[3]), "r"(b[0]), "r"(b[1]));
}

// ---------------- adj -> bf16 (hi only), float4 -----------------------------
__global__ void conv_vec4(const float* __restrict__ x,
                          __nv_bfloat16* __restrict__ hi, int n4)
{
    int i = blockIdx.x * blockDim.x + threadIdx.x;
    if (i >= n4) return;
    float4 v = reinterpret_cast<const float4*>(x)[i];
    reinterpret_cast<__nv_bfloat162*>(hi)[2 * i + 0] =
        __halves2bfloat162(__float2bfloat16(v.x), __float2bfloat16(v.y));
    reinterpret_cast<__nv_bfloat162*>(hi)[2 * i + 1] =
        __halves2bfloat162(__float2bfloat16(v.z), __float2bfloat16(v.w));
}

// ---------------- split-K partial reduce + activation -----------------------
// out[i] = act( sum_{p<S} in[p*MN + i] ), float4-vectorized.
template <int ACT, int S>
__global__ void reduce_act(const float* __restrict__ in,
                           float* __restrict__ out, int n4)
{
    int i = blockIdx.x * blockDim.x + threadIdx.x;
    if (i >= n4) return;
    float4 a = reinterpret_cast<const float4*>(in)[i];
    #pragma unroll
    for (int p = 1; p < S; p++) {
        float4 b = reinterpret_cast<const float4*>(in)[(size_t)p * n4 + i];
        a.x += b.x; a.y += b.y; a.z += b.z; a.w += b.w;
    }
    if (ACT == 1) {
        a.x = tanhf(a.x); a.y = tanhf(a.y); a.z = tanhf(a.z); a.w = tanhf(a.w);
    }
    reinterpret_cast<float4*>(out)[i] = a;
}

// ---------------- transpose + split: T[Kt,Nn] fp32 -> hi/lo [Nn,Kt] bf16 ----
__global__ void tsplit_kernel(const float* __restrict__ T, int Kt, int Nn,
                              __nv_bfloat16* __restrict__ hi,
                              __nv_bfloat16* __restrict__ lo)
{
    __shared__ float sm[32][33];
    int tx = threadIdx.x & 31;
    int ty = threadIdx.x >> 5;
    int k0 = blockIdx.y * 32;
    int n0 = blockIdx.x * 32;
    #pragma unroll
    for (int r = 0; r < 4; r++) {
        int row = k0 + ty + r * 8;
        int col = n0 + tx;
        sm[ty + r * 8][tx] = (row < Kt && col < Nn) ? T[(size_t)row * Nn + col] : 0.0f;
    }
    __syncthreads();
    #pragma unroll
    for (int r = 0; r < 4; r++) {
        int n = n0 + ty + r * 8;
        int k = k0 + tx;
        if (n < Nn && k < Kt) {
            float v = sm[tx][ty + r * 8];
            __nv_bfloat16 h, l;
            split2(v, h, l);
            hi[(size_t)n * Kt + k] = h;
            lo[(size_t)n * Kt + k] = l;
        }
    }
}

// ---------------- tensor-core split-bf16 GEMM -------------------------------
// C[M,N] = A[M,K] @ B[N,K]^T. ACT: 0 none, 1 tanh, 2 sigmoid.
// WSPLIT: also write bf16 split of C. MIRROR: triangular grid + mirror store.
// ASPLIT: 1 -> 3-term (AH*BH + AH*BL + AL*BH); 0 -> 2-term (A*(BH+BL)).
// kseg > 0: split-K. blockIdx.z selects K segment [z*kseg, min(K,(z+1)*kseg));
//           partial written to C + z*M*ldc (fp32, no act; reduce separately).
template <int ACT, int WSPLIT, int MIRROR, int ASPLIT>
__global__ __launch_bounds__(256, ASPLIT ? 1 : 2) void mma_gemm(
    const __nv_bfloat16* __restrict__ Ahi, const __nv_bfloat16* __restrict__ Alo, int lda,
    const __nv_bfloat16* __restrict__ Bhi, const __nv_bfloat16* __restrict__ Blo, int ldb,
    float* __restrict__ C, int ldc,
    __nv_bfloat16* __restrict__ Shi, __nv_bfloat16* __restrict__ Slo, int lds,
    int M, int N, int K, int kseg)
{
    extern __shared__ char smem[];
    constexpr int NARR = ASPLIT ? 4 : 3;
    constexpr int STAGE = NARR * ARR_BYTES;

    const int t    = threadIdx.x;
    const int lane = t & 31;
    const int wid  = t >> 5;
    const int wm   = (wid >> 2) * 64;
    const int wn   = (wid & 3) * 32;
    const int g    = lane >> 2;
    const int tg   = lane & 3;

    // split-K segment selection
    if (kseg > 0) {
        int kb = blockIdx.z * kseg;
        Ahi += kb;
        Bhi += kb;
        Blo += kb;
        if (ASPLIT) Alo += kb;
        C += (size_t)blockIdx.z * M * ldc;
        K = min(K - kb, kseg);
    }

    int bx, by;
    if (MIRROR) {
        int bid = blockIdx.x;
        by = (int)((sqrtf(8.0f * (float)bid + 1.0f) - 1.0f) * 0.5f);
        while ((by + 1) * (by + 2) / 2 <= bid) by++;
        while (by * (by + 1) / 2 > bid) by--;
        bx = bid - by * (by + 1) / 2;
    } else {
        bx = blockIdx.x;
        by = blockIdx.y;
    }
    const int m0 = by * 128;
    const int n0 = bx * 128;

    float acc[4][4][4];
    #pragma unroll
    for (int i = 0; i < 4; i++)
        #pragma unroll
        for (int j = 0; j < 4; j++)
            #pragma unroll
            for (int c = 0; c < 4; c++) acc[i][j][c] = 0.0f;

    // ldmatrix lane addressing
    const int a_row = lane & 15;
    const int a_c8  = (lane >> 4) * 8;
    const int b_row = (lane & 7) + ((lane >> 4) << 3);
    const int b_c8  = ((lane >> 3) & 1) * 8;

    const int ntiles = (K + 31) / 32;

    // ---- stage loader (cp.async): NARR arrays x 512 16B-chunks ----
    auto load_stage = [&](int s, int k0) {
        uint32_t base = (uint32_t)__cvta_generic_to_shared(smem) + s * STAGE;
        #pragma unroll
        for (int it = 0; it < 2 * NARR; it++) {
            int idx = t + it * 256;
            int arr = idx >> 9;             // 0..NARR-1
            int rem = idx & 511;
            int r   = rem >> 2;             // 0..127
            int c8  = (rem & 3) * 8;
            int gk  = k0 + c8;
            int kok = (gk < K);
            const __nv_bfloat16* src;
            int ok;
            if (ASPLIT) {
                if (arr < 2) {
                    int ga = m0 + r;
                    ok  = kok && (ga < M);
                    src = (arr == 0 ? Ahi : Alo) + (ok ? ((size_t)ga * lda + gk) : 0);
                } else {
                    int gb = n0 + r;
                    ok  = kok && (gb < N);
                    src = (arr == 2 ? Bhi : Blo) + (ok ? ((size_t)gb * ldb + gk) : 0);
                }
            } else {
                if (arr == 0) {
                    int ga = m0 + r;
                    ok  = kok && (ga < M);
                    src = Ahi + (ok ? ((size_t)ga * lda + gk) : 0);
                } else {
                    int gb = n0 + r;
                    ok  = kok && (gb < N);
                    src = (arr == 1 ? Bhi : Blo) + (ok ? ((size_t)gb * ldb + gk) : 0);
                }
            }
            uint32_t so = (uint32_t)(r * SSTR + c8) * 2;
            cp16(base + (uint32_t)arr * ARR_BYTES + so, src, ok);
        }
    };

    load_stage(0, 0);
    cp_commit();

    int s = 0;
    for (int kt = 0; kt < ntiles; kt++) {
        __syncthreads();
        load_stage(s ^ 1, (kt + 1) * 32);
        cp_commit();
        cp_wait1();
        __syncthreads();

        const char* sb = smem + s * STAGE;
        const __nv_bfloat16* sAH = (const __nv_bfloat16*)(sb);
        const __nv_bfloat16* sAL = (const __nv_bfloat16*)(sb + ARR_BYTES);  // ASPLIT only
        const __nv_bfloat16* sBH = (const __nv_bfloat16*)(sb + (NARR - 2) * ARR_BYTES);
        const __nv_bfloat16* sBL = (const __nv_bfloat16*)(sb + (NARR - 1) * ARR_BYTES);

        #pragma unroll
        for (int ks = 0; ks < 32; ks += 16) {
            uint32_t ah[4][4], al[4][4], bh[2][4], bl[2][4];
            #pragma unroll
            for (int i = 0; i < 4; i++) {
                int off = (wm + i * 16 + a_row) * SSTR + ks + a_c8;
                ldsm4(ah[i][0], ah[i][1], ah[i][2], ah[i][3],
                      (uint32_t)__cvta_generic_to_shared(sAH + off));
                if (ASPLIT)
                    ldsm4(al[i][0], al[i][1], al[i][2], al[i][3],
                          (uint32_t)__cvta_generic_to_shared(sAL + off));
            }
            #pragma unroll
            for (int jp = 0; jp < 2; jp++) {
                int off = (wn + jp * 16 + b_row) * SSTR + ks + b_c8;
                ldsm4(bh[jp][0], bh[jp][1], bh[jp][2], bh[jp][3],
                      (uint32_t)__cvta_generic_to_shared(sBH + off));
                ldsm4(bl[jp][0], bl[jp][1], bl[jp][2], bl[jp][3],
                      (uint32_t)__cvta_generic_to_shared(sBL + off));
            }
            #pragma unroll
            for (int i = 0; i < 4; i++)
                #pragma unroll
                for (int j = 0; j < 4; j++)
                    mma16816(acc[i][j], ah[i], &bh[j >> 1][(j & 1) * 2]);
            #pragma unroll
            for (int i = 0; i < 4; i++)
                #pragma unroll
                for (int j = 0; j < 4; j++)
                    mma16816(acc[i][j], ah[i], &bl[j >> 1][(j & 1) * 2]);
            if (ASPLIT) {
                #pragma unroll
                for (int i = 0; i < 4; i++)
                    #pragma unroll
                    for (int j = 0; j < 4; j++)
                        mma16816(acc[i][j], al[i], &bh[j >> 1][(j & 1) * 2]);
            }
        }
        s ^= 1;
    }

    const bool do_mirror = MIRROR && (bx != by);
    float* tile = (float*)smem;       // 128 x 132 fp32 (fits in SMEM4 path)
    if (do_mirror) __syncthreads();

    // ---- epilogue ----
    #pragma unroll
    for (int i = 0; i < 4; i++) {
        #pragma unroll
        for (int j = 0; j < 4; j++) {
            int nl = wn + j * 8 + 2 * tg;
            int cn = n0 + nl;
            if (cn >= N) continue;
            #pragma unroll
            for (int h = 0; h < 2; h++) {
                int ml = wm + i * 16 + g + h * 8;
                int rm = m0 + ml;
                if (rm >= M) continue;
                float v0 = acc[i][j][2 * h + 0];
                float v1 = acc[i][j][2 * h + 1];
                if (ACT == 1) { v0 = tanhf(v0); v1 = tanhf(v1); }
                else if (ACT == 2) {
                    v0 = 1.0f / (1.0f + expf(-v0));
                    v1 = 1.0f / (1.0f + expf(-v1));
                }
                C[(size_t)rm * ldc + cn]     = v0;
                C[(size_t)rm * ldc + cn + 1] = v1;
                if (do_mirror) {
                    tile[(nl + 0) * 132 + ml] = v0;
                    tile[(nl + 1) * 132 + ml] = v1;
                }
                if (WSPLIT) {
                    __nv_bfloat16 hh, ll;
                    split2(v0, hh, ll);
                    Shi[(size_t)rm * lds + cn] = hh;
                    Slo[(size_t)rm * lds + cn] = ll;
                    split2(v1, hh, ll);
                    Shi[(size_t)rm * lds + cn + 1] = hh;
                    Slo[(size_t)rm * lds + cn + 1] = ll;
                }
            }
        }
    }

    if (do_mirror) {
        __syncthreads();
        for (int i = t; i < 128 * 32; i += 256) {
            int r  = i >> 5;
            int c4 = (i & 31) * 4;
            int gr = n0 + r;
            int gc = m0 + c4;
            if (gr < N && gc < M) {
                float4 v = *reinterpret_cast<const float4*>(&tile[r * 132 + c4]);
                *reinterpret_cast<float4*>(&C[(size_t)gr * ldc + gc]) = v;
            }
        }
    }
}

// ---------------- small fp32 SIMT GEMM (NN, no act) for X @ W ---------------
#define BM 128
#define BN 128
#define BK 8
__global__ __launch_bounds__(256) void simt_gemm(
    const float* __restrict__ A, const float* __restrict__ B,
    float* __restrict__ C, int M, int N, int K)
{
    __shared__ float As[BK][BM];
    __shared__ float Bs[BK][BN];
    const int t  = threadIdx.x;
    const int m0 = blockIdx.y * BM;
    const int n0 = blockIdx.x * BN;
    const int ar = t >> 1, ac = (t & 1) * 4;
    const int br = t >> 5, bc = (t & 31) * 4;
    const int ty = t >> 4, tx = t & 15;

    float acc[8][8];
    #pragma unroll
    for (int i = 0; i < 8; i++)
        #pragma unroll
        for (int j = 0; j < 8; j++) acc[i][j] = 0.0f;

    for (int k0 = 0; k0 < K; k0 += BK) {
        float4 av = make_float4(0.f, 0.f, 0.f, 0.f);
        if (m0 + ar < M && k0 + ac < K)
            av = *reinterpret_cast<const float4*>(A + (size_t)(m0 + ar) * K + k0 + ac);
        As[ac + 0][ar] = av.x; As[ac + 1][ar] = av.y;
        As[ac + 2][ar] = av.z; As[ac + 3][ar] = av.w;
        float4 bv = make_float4(0.f, 0.f, 0.f, 0.f);
        if (k0 + br < K && n0 + bc < N)
            bv = *reinterpret_cast<const float4*>(B + (size_t)(k0 + br) * N + n0 + bc);
        *reinterpret_cast<float4*>(&Bs[br][bc]) = bv;
        __syncthreads();
        #pragma unroll
        for (int kk = 0; kk < BK; kk++) {
            float a[8], b[8];
            *reinterpret_cast<float4*>(&a[0]) = *reinterpret_cast<const float4*>(&As[kk][ty * 8]);
            *reinterpret_cast<float4*>(&a[4]) = *reinterpret_cast<const float4*>(&As[kk][ty * 8 + 4]);
            *reinterpret_cast<float4*>(&b[0]) = *reinterpret_cast<const float4*>(&Bs[kk][tx * 8]);
            *reinterpret_cast<float4*>(&b[4]) = *reinterpret_cast<const float4*>(&Bs[kk][tx * 8 + 4]);
            #pragma unroll
            for (int i = 0; i < 8; i++)
                #pragma unroll
                for (int j = 0; j < 8; j++)
                    acc[i][j] = fmaf(a[i], b[j], acc[i][j]);
        }
        __syncthreads();
    }
    #pragma unroll
    for (int i = 0; i < 8; i++) {
        int m = m0 + ty * 8 + i;
        if (m >= M) continue;
        #pragma unroll
        for (int j = 0; j < 8; j++) {
            int n = n0 + tx * 8 + j;
            if (n < N) C[(size_t)m * N + n] = acc[i][j];
        }
    }
}

// ---------------- driver -----------------------------------------------------
extern "C" void kernel_launch(void* const* d_in, const int* in_sizes, int n_in,
                              void* d_out, int out_size)
{
    const float* z_igae = (const float*)d_in[0];  // [10000, 20]
    const float* adj    = (const float*)d_in[1];  // [10000, 10000]
    const float* w3     = (const float*)d_in[2];  // [20, 256]
    const float* w4     = (const float*)d_in[3];  // [256, 128]
    const float* w5     = (const float*)d_in[4];  // [128, 500]

    float* out      = (float*)d_out;
    float* z_hat    = out;                          // [10000, 500]
    float* z_hatadj = out + (size_t)NROWS * 500;    // [10000, 10000]

    __nv_bfloat16 *adjH, *btH, *btL, *zhH, *zhL;
    float *f1, *f2;
    cudaGetSymbolAddress((void**)&adjH, g_adj_hi);
    cudaGetSymbolAddress((void**)&btH,  g_bt_hi);
    cudaGetSymbolAddress((void**)&btL,  g_bt_lo);
    cudaGetSymbolAddress((void**)&zhH,  g_zh_hi);
    cudaGetSymbolAddress((void**)&zhL,  g_zh_lo);
    cudaGetSymbolAddress((void**)&f1,   g_f1);
    cudaGetSymbolAddress((void**)&f2,   g_f2);

    cudaFuncSetAttribute(mma_gemm<0, 0, 0, 0>,
                         cudaFuncAttributeMaxDynamicSharedMemorySize, SMEM3);
    cudaFuncSetAttribute(mma_gemm<0, 1, 0, 0>,
                         cudaFuncAttributeMaxDynamicSharedMemorySize, SMEM3);
    cudaFuncSetAttribute(mma_gemm<2, 0, 1, 1>,
                         cudaFuncAttributeMaxDynamicSharedMemorySize, SMEM4);

    // 0. adj -> bf16 (hi only)
    {
        int n4 = (int)(ADJ_N / 4);
        conv_vec4<<<(n4 + 255) / 256, 256>>>(adj, adjH, n4);
    }

    dim3 blk(256);

    // 1. T1 = z_igae @ w3  [10000,256]
    simt_gemm<<<dim3(2, 79), blk>>>(z_igae, w3, f1, NROWS, 256, 20);
    // 2. transpose+split T1 -> [256,10000]
    tsplit_kernel<<<dim3(8, 313), blk>>>(f1, NROWS, 256, btH, btL);
    // 3. Z1 = tanh(adj @ T1): split-K=2 partials into f1, then reduce+tanh
    //    (f1 free after tsplit; [2][10000][256] = 10000*512 floats exactly)
    mma_gemm<0, 0, 0, 0><<<dim3(2, 79, 2), blk, SMEM3>>>(
        adjH, nullptr, NROWS, btH, btL, NROWS,
        f1, 256, nullptr, nullptr, 0, NROWS, 256, NROWS, 5024);
    reduce_act<1, 2><<<(NROWS * 256 / 4 + 255) / 256, blk>>>(f1, f2, NROWS * 256 / 4);
    // 4. T2 = Z1 @ w4  [10000,128]  (overwrites f1 partials — consumed)
    //    NOTE: f1 reused; simt writes [10000,128] at f1 start.
    simt_gemm<<<dim3(1, 79), blk>>>(f2, w4, f1, NROWS, 128, 256);
    // 5. transpose+split T2 -> [128,10000]
    tsplit_kernel<<<dim3(4, 313), blk>>>(f1, NROWS, 128, btH, btL);
    // 6. Z2 = tanh(adj @ T2): split-K=4 partials into f1, reduce+tanh -> f2
    mma_gemm<0, 0, 0, 0><<<dim3(1, 79, 4), blk, SMEM3>>>(
        adjH, nullptr, NROWS, btH, btL, NROWS,
        f1, 128, nullptr, nullptr, 0, NROWS, 128, NROWS, 2528);
    reduce_act<1, 4><<<(NROWS * 128 / 4 + 255) / 256, blk>>>(f1, f2, NROWS * 128 / 4);
    // 7. T3 = Z2 @ w5  [10000,500]
    simt_gemm<<<dim3(4, 79), blk>>>(f2, w5, f1, NROWS, 500, 128);
    // 8. transpose+split T3 -> [500,10000]
    tsplit_kernel<<<dim3(16, 313), blk>>>(f1, NROWS, 500, btH, btL);
    // 9. z_hat = adj @ T3  [10000,500] (grid 316 — no split needed), 2-term,
    //    fused bf16 split (lds=512, pads stay 0)
    mma_gemm<0, 1, 0, 0><<<dim3(4, 79), blk, SMEM3>>>(
        adjH, nullptr, NROWS, btH, btL, NROWS,
        z_hat, 500, zhH, zhL, 512, NROWS, 500, NROWS, 0);
    // 10. z_hat_adj = sigmoid(z_hat @ z_hat^T): 3-term, triangular + mirror
    {
        int nblk = 79 * 80 / 2;  // 3160
        mma_gemm<2, 0, 1, 1><<<dim3(nblk), blk, SMEM4>>>(
            zhH, zhL, 512, zhH, zhL, 512,
            z_hatadj, NROWS, nullptr, nullptr, 0, NROWS, NROWS, 512, 0);
    }
}

// round 8
// speedup vs baseline: 1.9008x; 1.2216x over previous
#include <cuda_runtime.h>
#include <cuda_bf16.h>
#include <math.h>
#include <stdint.h>

// ============================================================================
// GCN decoder chain. Tensor-core GEMMs via mma.sync m16n8k16 bf16.
// Round 8: wave-balanced split-K on ALL adj-GEMMs (296 co-residency slots;
// grids of 316 were paying a 2x straggler wave), syrk at 2 CTAs/SM.
// adj-GEMMs: 2-term split  C = adj_bf16 @ (Bhi + Blo). Syrk: 3-term split.
// NOTE: tcgen05 unavailable — harness ptxas targets sm_103 (no 'a').
// ============================================================================

#define NROWS 10000
#define ADJ_N 100000000LL
#define SSTR 40                       // smem k-stride (bf16), conflict-free
#define ARR_BYTES (128 * SSTR * 2)    // 10240 per operand array
#define SMEM3 (2 * 3 * ARR_BYTES)     // 61440: 2 stages x {A, BH, BL}
#define SMEM4 (2 * 4 * ARR_BYTES)     // 81920: 2 stages x {AH, AL, BH, BL}

// ---------------- scratch (static __device__, allocation-free) -------------
__device__ __nv_bfloat16 g_adj_hi[100000000];
__device__ __nv_bfloat16 g_bt_hi[500 * 10000];
__device__ __nv_bfloat16 g_bt_lo[500 * 10000];
__device__ __nv_bfloat16 g_zh_hi[10000 * 512];   // pads (cols 500..511) stay 0
__device__ __nv_bfloat16 g_zh_lo[10000 * 512];
__device__ float g_f1[10000 * 512];
__device__ float g_f2[10000 * 512];
__device__ float g_part[10240000];               // split-K partials (41 MB)

// ---------------- helpers ----------------------------------------------------
__device__ __forceinline__ void split2(float x, __nv_bfloat16& h, __nv_bfloat16& l) {
    h = __float2bfloat16(x);
    l = __float2bfloat16(x - __bfloat162float(h));
}

__device__ __forceinline__ void cp16(uint32_t daddr, const void* src, int ok) {
    int sz = ok ? 16 : 0;
    asm volatile("cp.async.cg.shared.global [%0], [%1], 16, %2;"
                 :: "r"(daddr), "l"(src), "r"(sz));
}
__device__ __forceinline__ void cp_commit() {
    asm volatile("cp.async.commit_group;");
}
__device__ __forceinline__ void cp_wait1() {
    asm volatile("cp.async.wait_group 1;");
}
__device__ __forceinline__ void ldsm4(uint32_t& r0, uint32_t& r1, uint32_t& r2,
                                      uint32_t& r3, uint32_t addr) {
    asm volatile("ldmatrix.sync.aligned.m8n8.x4.shared.b16 {%0,%1,%2,%3}, [%4];"
                 : "=r"(r0), "=r"(r1), "=r"(r2), "=r"(r3) : "r"(addr));
}
__device__ __forceinline__ void mma16816(float c[4], const uint32_t a[4],
                                         const uint32_t b[2]) {
    asm volatile(
        "mma.sync.aligned.m16n8k16.row.col.f32.bf16.bf16.f32 "
        "{%0,%1,%2,%3}, {%4,%5,%6,%7}, {%8,%9}, {%0,%1,%2,%3};"
        : "+f"(c[0]), "+f"(c[1]), "+f"(c[2]), "+f"(c[3])
        : "r"(a[0]), "r"(a[1]), "r"(a[2]), "r"(a[3]), "r"(b[0]), "r"(b[1]));
}

// ---------------- adj -> bf16 (hi only), float4 -----------------------------
__global__ void conv_vec4(const float* __restrict__ x,
                          __nv_bfloat16* __restrict__ hi, int n4)
{
    int i = blockIdx.x * blockDim.x + threadIdx.x;
    if (i >= n4) return;
    float4 v = reinterpret_cast<const float4*>(x)[i];
    reinterpret_cast<__nv_bfloat162*>(hi)[2 * i + 0] =
        __halves2bfloat162(__float2bfloat16(v.x), __float2bfloat16(v.y));
    reinterpret_cast<__nv_bfloat162*>(hi)[2 * i + 1] =
        __halves2bfloat162(__float2bfloat16(v.z), __float2bfloat16(v.w));
}

// ---------------- split-K partial reduce + activation (+optional split) -----
// out[i] = act( sum_{p<S} in[p*stride + i] ), float4-vectorized over n4 quads.
// WSP: also write bf16 hi/lo split to [row, col] with row stride lds
//      (row = elem/ncols, col = elem%ncols for the [M, ncols] logical array).
template <int ACT, int S, int WSP>
__global__ void reduce_act(const float* __restrict__ in, long long stride,
                           float* __restrict__ out, int n4,
                           __nv_bfloat16* __restrict__ hi,
                           __nv_bfloat16* __restrict__ lo,
                           int ncols, int lds)
{
    int i = blockIdx.x * blockDim.x + threadIdx.x;
    if (i >= n4) return;
    float4 a = reinterpret_cast<const float4*>(in)[i];
    #pragma unroll
    for (int p = 1; p < S; p++) {
        float4 b = reinterpret_cast<const float4*>(in + (long long)p * stride)[i];
        a.x += b.x; a.y += b.y; a.z += b.z; a.w += b.w;
    }
    if (ACT == 1) {
        a.x = tanhf(a.x); a.y = tanhf(a.y); a.z = tanhf(a.z); a.w = tanhf(a.w);
    }
    reinterpret_cast<float4*>(out)[i] = a;
    if (WSP) {
        int e   = i * 4;
        int row = e / ncols;
        int col = e - row * ncols;       // ncols % 4 == 0 -> quad in one row
        float v[4] = {a.x, a.y, a.z, a.w};
        #pragma unroll
        for (int q = 0; q < 4; q++) {
            __nv_bfloat16 h, l;
            split2(v[q], h, l);
            hi[(size_t)row * lds + col + q] = h;
            lo[(size_t)row * lds + col + q] = l;
        }
    }
}

// ---------------- transpose + split: T[Kt,Nn] fp32 -> hi/lo [Nn,Kt] bf16 ----
__global__ void tsplit_kernel(const float* __restrict__ T, int Kt, int Nn,
                              __nv_bfloat16* __restrict__ hi,
                              __nv_bfloat16* __restrict__ lo)
{
    __shared__ float sm[32][33];
    int tx = threadIdx.x & 31;
    int ty = threadIdx.x >> 5;
    int k0 = blockIdx.y * 32;
    int n0 = blockIdx.x * 32;
    #pragma unroll
    for (int r = 0; r < 4; r++) {
        int row = k0 + ty + r * 8;
        int col = n0 + tx;
        sm[ty + r * 8][tx] = (row < Kt && col < Nn) ? T[(size_t)row * Nn + col] : 0.0f;
    }
    __syncthreads();
    #pragma unroll
    for (int r = 0; r < 4; r++) {
        int n = n0 + ty + r * 8;
        int k = k0 + tx;
        if (n < Nn && k < Kt) {
            float v = sm[tx][ty + r * 8];
            __nv_bfloat16 h, l;
            split2(v, h, l);
            hi[(size_t)n * Kt + k] = h;
            lo[(size_t)n * Kt + k] = l;
        }
    }
}

// ---------------- tensor-core split-bf16 GEMM -------------------------------
// C[M,N] = A[M,K] @ B[N,K]^T. ACT: 0 none, 1 tanh, 2 sigmoid.
// WSPLIT: also write bf16 split of C. MIRROR: triangular grid + mirror store.
// ASPLIT: 1 -> 3-term (AH*BH + AH*BL + AL*BH); 0 -> 2-term (A*(BH+BL)).
// kseg > 0: split-K; blockIdx.z segment [z*kseg, ...); partial -> C + z*M*ldc.
template <int ACT, int WSPLIT, int MIRROR, int ASPLIT>
__global__ __launch_bounds__(256, 2) void mma_gemm(
    const __nv_bfloat16* __restrict__ Ahi, const __nv_bfloat16* __restrict__ Alo, int lda,
    const __nv_bfloat16* __restrict__ Bhi, const __nv_bfloat16* __restrict__ Blo, int ldb,
    float* __restrict__ C, int ldc,
    __nv_bfloat16* __restrict__ Shi, __nv_bfloat16* __restrict__ Slo, int lds,
    int M, int N, int K, int kseg)
{
    extern __shared__ char smem[];
    constexpr int NARR = ASPLIT ? 4 : 3;
    constexpr int STAGE = NARR * ARR_BYTES;

    const int t    = threadIdx.x;
    const int lane = t & 31;
    const int wid  = t >> 5;
    const int wm   = (wid >> 2) * 64;
    const int wn   = (wid & 3) * 32;
    const int g    = lane >> 2;
    const int tg   = lane & 3;

    if (kseg > 0) {
        int kb = blockIdx.z * kseg;
        Ahi += kb;
        Bhi += kb;
        Blo += kb;
        if (ASPLIT) Alo += kb;
        C += (size_t)blockIdx.z * M * ldc;
        K = min(K - kb, kseg);
    }

    int bx, by;
    if (MIRROR) {
        int bid = blockIdx.x;
        by = (int)((sqrtf(8.0f * (float)bid + 1.0f) - 1.0f) * 0.5f);
        while ((by + 1) * (by + 2) / 2 <= bid) by++;
        while (by * (by + 1) / 2 > bid) by--;
        bx = bid - by * (by + 1) / 2;
    } else {
        bx = blockIdx.x;
        by = blockIdx.y;
    }
    const int m0 = by * 128;
    const int n0 = bx * 128;

    float acc[4][4][4];
    #pragma unroll
    for (int i = 0; i < 4; i++)
        #pragma unroll
        for (int j = 0; j < 4; j++)
            #pragma unroll
            for (int c = 0; c < 4; c++) acc[i][j][c] = 0.0f;

    const int a_row = lane & 15;
    const int a_c8  = (lane >> 4) * 8;
    const int b_row = (lane & 7) + ((lane >> 4) << 3);
    const int b_c8  = ((lane >> 3) & 1) * 8;

    const int ntiles = (K + 31) / 32;

    auto load_stage = [&](int s, int k0) {
        uint32_t base = (uint32_t)__cvta_generic_to_shared(smem) + s * STAGE;
        #pragma unroll
        for (int it = 0; it < 2 * NARR; it++) {
            int idx = t + it * 256;
            int arr = idx >> 9;
            int rem = idx & 511;
            int r   = rem >> 2;
            int c8  = (rem & 3) * 8;
            int gk  = k0 + c8;
            int kok = (gk < K);
            const __nv_bfloat16* src;
            int ok;
            if (ASPLIT) {
                if (arr < 2) {
                    int ga = m0 + r;
                    ok  = kok && (ga < M);
                    src = (arr == 0 ? Ahi : Alo) + (ok ? ((size_t)ga * lda + gk) : 0);
                } else {
                    int gb = n0 + r;
                    ok  = kok && (gb < N);
                    src = (arr == 2 ? Bhi : Blo) + (ok ? ((size_t)gb * ldb + gk) : 0);
                }
            } else {
                if (arr == 0) {
                    int ga = m0 + r;
                    ok  = kok && (ga < M);
                    src = Ahi + (ok ? ((size_t)ga * lda + gk) : 0);
                } else {
                    int gb = n0 + r;
                    ok  = kok && (gb < N);
                    src = (arr == 1 ? Bhi : Blo) + (ok ? ((size_t)gb * ldb + gk) : 0);
                }
            }
            uint32_t so = (uint32_t)(r * SSTR + c8) * 2;
            cp16(base + (uint32_t)arr * ARR_BYTES + so, src, ok);
        }
    };

    load_stage(0, 0);
    cp_commit();

    int s = 0;
    for (int kt = 0; kt < ntiles; kt++) {
        __syncthreads();
        load_stage(s ^ 1, (kt + 1) * 32);
        cp_commit();
        cp_wait1();
        __syncthreads();

        const char* sb = smem + s * STAGE;
        const __nv_bfloat16* sAH = (const __nv_bfloat16*)(sb);
        const __nv_bfloat16* sAL = (const __nv_bfloat16*)(sb + ARR_BYTES);
        const __nv_bfloat16* sBH = (const __nv_bfloat16*)(sb + (NARR - 2) * ARR_BYTES);
        const __nv_bfloat16* sBL = (const __nv_bfloat16*)(sb + (NARR - 1) * ARR_BYTES);

        #pragma unroll
        for (int ks = 0; ks < 32; ks += 16) {
            uint32_t ah[4][4], al[4][4], bh[2][4], bl[2][4];
            #pragma unroll
            for (int i = 0; i < 4; i++) {
                int off = (wm + i * 16 + a_row) * SSTR + ks + a_c8;
                ldsm4(ah[i][0], ah[i][1], ah[i][2], ah[i][3],
                      (uint32_t)__cvta_generic_to_shared(sAH + off));
                if (ASPLIT)
                    ldsm4(al[i][0], al[i][1], al[i][2], al[i][3],
                          (uint32_t)__cvta_generic_to_shared(sAL + off));
            }
            #pragma unroll
            for (int jp = 0; jp < 2; jp++) {
                int off = (wn + jp * 16 + b_row) * SSTR + ks + b_c8;
                ldsm4(bh[jp][0], bh[jp][1], bh[jp][2], bh[jp][3],
                      (uint32_t)__cvta_generic_to_shared(sBH + off));
                ldsm4(bl[jp][0], bl[jp][1], bl[jp][2], bl[jp][3],
                      (uint32_t)__cvta_generic_to_shared(sBL + off));
            }
            #pragma unroll
            for (int i = 0; i < 4; i++)
                #pragma unroll
                for (int j = 0; j < 4; j++)
                    mma16816(acc[i][j], ah[i], &bh[j >> 1][(j & 1) * 2]);
            #pragma unroll
            for (int i = 0; i < 4; i++)
                #pragma unroll
                for (int j = 0; j < 4; j++)
                    mma16816(acc[i][j], ah[i], &bl[j >> 1][(j & 1) * 2]);
            if (ASPLIT) {
                #pragma unroll
                for (int i = 0; i < 4; i++)
                    #pragma unroll
                    for (int j = 0; j < 4; j++)
                        mma16816(acc[i][j], al[i], &bh[j >> 1][(j & 1) * 2]);
            }
        }
        s ^= 1;
    }

    const bool do_mirror = MIRROR && (bx != by);
    float* tile = (float*)smem;
    if (do_mirror) __syncthreads();

    #pragma unroll
    for (int i = 0; i < 4; i++) {
        #pragma unroll
        for (int j = 0; j < 4; j++) {
            int nl = wn + j * 8 + 2 * tg;
            int cn = n0 + nl;
            if (cn >= N) continue;
            #pragma unroll
            for (int h = 0; h < 2; h++) {
                int ml = wm + i * 16 + g + h * 8;
                int rm = m0 + ml;
                if (rm >= M) continue;
                float v0 = acc[i][j][2 * h + 0];
                float v1 = acc[i][j][2 * h + 1];
                if (ACT == 1) { v0 = tanhf(v0); v1 = tanhf(v1); }
                else if (ACT == 2) {
                    v0 = 1.0f / (1.0f + expf(-v0));
                    v1 = 1.0f / (1.0f + expf(-v1));
                }
                C[(size_t)rm * ldc + cn]     = v0;
                C[(size_t)rm * ldc + cn + 1] = v1;
                if (do_mirror) {
                    tile[(nl + 0) * 132 + ml] = v0;
                    tile[(nl + 1) * 132 + ml] = v1;
                }
                if (WSPLIT) {
                    __nv_bfloat16 hh, ll;
                    split2(v0, hh, ll);
                    Shi[(size_t)rm * lds + cn] = hh;
                    Slo[(size_t)rm * lds + cn] = ll;
                    split2(v1, hh, ll);
                    Shi[(size_t)rm * lds + cn + 1] = hh;
                    Slo[(size_t)rm * lds + cn + 1] = ll;
                }
            }
        }
    }

    if (do_mirror) {
        __syncthreads();
        for (int i = t; i < 128 * 32; i += 256) {
            int r  = i >> 5;
            int c4 = (i & 31) * 4;
            int gr = n0 + r;
            int gc = m0 + c4;
            if (gr < N && gc < M) {
                float4 v = *reinterpret_cast<const float4*>(&tile[r * 132 + c4]);
                *reinterpret_cast<float4*>(&C[(size_t)gr * ldc + gc]) = v;
            }
        }
    }
}

// ---------------- small fp32 SIMT GEMM (NN, no act) for X @ W ---------------
#define BM 128
#define BN 128
#define BK 8
__global__ __launch_bounds__(256) void simt_gemm(
    const float* __restrict__ A, const float* __restrict__ B,
    float* __restrict__ C, int M, int N, int K)
{
    __shared__ float As[BK][BM];
    __shared__ float Bs[BK][BN];
    const int t  = threadIdx.x;
    const int m0 = blockIdx.y * BM;
    const int n0 = blockIdx.x * BN;
    const int ar = t >> 1, ac = (t & 1) * 4;
    const int br = t >> 5, bc = (t & 31) * 4;
    const int ty = t >> 4, tx = t & 15;

    float acc[8][8];
    #pragma unroll
    for (int i = 0; i < 8; i++)
        #pragma unroll
        for (int j = 0; j < 8; j++) acc[i][j] = 0.0f;

    for (int k0 = 0; k0 < K; k0 += BK) {
        float4 av = make_float4(0.f, 0.f, 0.f, 0.f);
        if (m0 + ar < M && k0 + ac < K)
            av = *reinterpret_cast<const float4*>(A + (size_t)(m0 + ar) * K + k0 + ac);
        As[ac + 0][ar] = av.x; As[ac + 1][ar] = av.y;
        As[ac + 2][ar] = av.z; As[ac + 3][ar] = av.w;
        float4 bv = make_float4(0.f, 0.f, 0.f, 0.f);
        if (k0 + br < K && n0 + bc < N)
            bv = *reinterpret_cast<const float4*>(B + (size_t)(k0 + br) * N + n0 + bc);
        *reinterpret_cast<float4*>(&Bs[br][bc]) = bv;
        __syncthreads();
        #pragma unroll
        for (int kk = 0; kk < BK; kk++) {
            float a[8], b[8];
            *reinterpret_cast<float4*>(&a[0]) = *reinterpret_cast<const float4*>(&As[kk][ty * 8]);
            *reinterpret_cast<float4*>(&a[4]) = *reinterpret_cast<const float4*>(&As[kk][ty * 8 + 4]);
            *reinterpret_cast<float4*>(&b[0]) = *reinterpret_cast<const float4*>(&Bs[kk][tx * 8]);
            *reinterpret_cast<float4*>(&b[4]) = *reinterpret_cast<const float4*>(&Bs[kk][tx * 8 + 4]);
            #pragma unroll
            for (int i = 0; i < 8; i++)
                #pragma unroll
                for (int j = 0; j < 8; j++)
                    acc[i][j] = fmaf(a[i], b[j], acc[i][j]);
        }
        __syncthreads();
    }
    #pragma unroll
    for (int i = 0; i < 8; i++) {
        int m = m0 + ty * 8 + i;
        if (m >= M) continue;
        #pragma unroll
        for (int j = 0; j < 8; j++) {
            int n = n0 + tx * 8 + j;
            if (n < N) C[(size_t)m * N + n] = acc[i][j];
        }
    }
}

// ---------------- driver -----------------------------------------------------
extern "C" void kernel_launch(void* const* d_in, const int* in_sizes, int n_in,
                              void* d_out, int out_size)
{
    const float* z_igae = (const float*)d_in[0];  // [10000, 20]
    const float* adj    = (const float*)d_in[1];  // [10000, 10000]
    const float* w3     = (const float*)d_in[2];  // [20, 256]
    const float* w4     = (const float*)d_in[3];  // [256, 128]
    const float* w5     = (const float*)d_in[4];  // [128, 500]

    float* out      = (float*)d_out;
    float* z_hat    = out;                          // [10000, 500]
    float* z_hatadj = out + (size_t)NROWS * 500;    // [10000, 10000]

    __nv_bfloat16 *adjH, *btH, *btL, *zhH, *zhL;
    float *f1, *f2, *part;
    cudaGetSymbolAddress((void**)&adjH, g_adj_hi);
    cudaGetSymbolAddress((void**)&btH,  g_bt_hi);
    cudaGetSymbolAddress((void**)&btL,  g_bt_lo);
    cudaGetSymbolAddress((void**)&zhH,  g_zh_hi);
    cudaGetSymbolAddress((void**)&zhL,  g_zh_lo);
    cudaGetSymbolAddress((void**)&f1,   g_f1);
    cudaGetSymbolAddress((void**)&f2,   g_f2);
    cudaGetSymbolAddress((void**)&part, g_part);

    cudaFuncSetAttribute(mma_gemm<0, 0, 0, 0>,
                         cudaFuncAttributeMaxDynamicSharedMemorySize, SMEM3);
    cudaFuncSetAttribute(mma_gemm<2, 0, 1, 1>,
                         cudaFuncAttributeMaxDynamicSharedMemorySize, SMEM4);

    // 0. adj -> bf16 (hi only)
    {
        int n4 = (int)(ADJ_N / 4);
        conv_vec4<<<(n4 + 255) / 256, 256>>>(adj, adjH, n4);
    }

    dim3 blk(256);

    // 1. T1 = z_igae @ w3  [10000,256]
    simt_gemm<<<dim3(2, 79), blk>>>(z_igae, w3, f1, NROWS, 256, 20);
    // 2. transpose+split T1 -> [256,10000]
    tsplit_kernel<<<dim3(8, 313), blk>>>(f1, NROWS, 256, btH, btL);
    // 3. Z1 = tanh(adj @ T1): split-K=4 (632 CTAs ~ 2.14 waves), reduce+tanh
    mma_gemm<0, 0, 0, 0><<<dim3(2, 79, 4), blk, SMEM3>>>(
        adjH, nullptr, NROWS, btH, btL, NROWS,
        part, 256, nullptr, nullptr, 0, NROWS, 256, NROWS, 2528);
    {
        int n4 = NROWS * 256 / 4;
        reduce_act<1, 4, 0><<<(n4 + 255) / 256, blk>>>(
            part, (long long)NROWS * 256, f2, n4, nullptr, nullptr, 0, 0);
    }
    // 4. T2 = Z1 @ w4  [10000,128]
    simt_gemm<<<dim3(1, 79), blk>>>(f2, w4, f1, NROWS, 128, 256);
    // 5. transpose+split T2 -> [128,10000]
    tsplit_kernel<<<dim3(4, 313), blk>>>(f1, NROWS, 128, btH, btL);
    // 6. Z2 = tanh(adj @ T2): split-K=8 (632 CTAs), reduce+tanh
    mma_gemm<0, 0, 0, 0><<<dim3(1, 79, 8), blk, SMEM3>>>(
        adjH, nullptr, NROWS, btH, btL, NROWS,
        part, 128, nullptr, nullptr, 0, NROWS, 128, NROWS, 1280);
    {
        int n4 = NROWS * 128 / 4;
        reduce_act<1, 8, 0><<<(n4 + 255) / 256, blk>>>(
            part, (long long)NROWS * 128, f2, n4, nullptr, nullptr, 0, 0);
    }
    // 7. T3 = Z2 @ w5  [10000,500]
    simt_gemm<<<dim3(4, 79), blk>>>(f2, w5, f1, NROWS, 500, 128);
    // 8. transpose+split T3 -> [500,10000]
    tsplit_kernel<<<dim3(16, 313), blk>>>(f1, NROWS, 500, btH, btL);
    // 9. z_hat = adj @ T3: split-K=2 (632 CTAs); reduce emits z_hat + bf16
    //    split (lds=512; pad cols stay 0 from static zero-init)
    mma_gemm<0, 0, 0, 0><<<dim3(4, 79, 2), blk, SMEM3>>>(
        adjH, nullptr, NROWS, btH, btL, NROWS,
        part, 500, nullptr, nullptr, 0, NROWS, 500, NROWS, 5024);
    {
        int n4 = NROWS * 500 / 4;
        reduce_act<0, 2, 1><<<(n4 + 255) / 256, blk>>>(
            part, (long long)NROWS * 500, z_hat, n4, zhH, zhL, 500, 512);
    }
    // 10. z_hat_adj = sigmoid(z_hat @ z_hat^T): 3-term, triangular + mirror,
    //     now 2 CTAs/SM (3160 CTAs ~ 10.7 waves)
    {
        int nblk = 79 * 80 / 2;  // 3160
        mma_gemm<2, 0, 1, 1><<<dim3(nblk), blk, SMEM4>>>(
            zhH, zhL, 512, zhH, zhL, 512,
            z_hatadj, NROWS, nullptr, nullptr, 0, NROWS, NROWS, 512, 0);
    }
}

// round 9
// speedup vs baseline: 2.0443x; 1.0755x over previous
#include <cuda_runtime.h>
#include <cuda_bf16.h>
#include <math.h>
#include <stdint.h>

// ============================================================================
// GCN decoder chain. Tensor-core GEMMs via mma.sync m16n8k16 bf16.
// Round 9: (a) finer split-K to cut ceil-wave quantization (L1 z=8, L2 z=16,
// L3 z=4; kseg multiples of 8 for cp.async 16B alignment); (b) syrk reduced
// to the same 2-term kernel (C = zhH @ (zhH+zhL)^T) — sigmoid(~0.5 + x/4) at
// tiny logits suppresses the dropped-term error. One unified 3-array GEMM.
// NOTE: tcgen05 unavailable — harness ptxas targets sm_103 (no 'a').
// ============================================================================

#define NROWS 10000
#define ADJ_N 100000000LL
#define SSTR 40                       // smem k-stride (bf16), conflict-free
#define ARR_BYTES (128 * SSTR * 2)    // 10240 per operand array
#define SMEM_G (2 * 3 * ARR_BYTES)    // 61440: 2 stages x {A, BH, BL}
#define SMEM_MIR (128 * 132 * 4)      // 67584: mirror tile (syrk launch size)

// ---------------- scratch (static __device__, allocation-free) -------------
__device__ __nv_bfloat16 g_adj_hi[100000000];
__device__ __nv_bfloat16 g_bt_hi[500 * 10000];
__device__ __nv_bfloat16 g_bt_lo[500 * 10000];
__device__ __nv_bfloat16 g_zh_hi[10000 * 512];   // pads (cols 500..511) stay 0
__device__ __nv_bfloat16 g_zh_lo[10000 * 512];
__device__ float g_f1[10000 * 512];
__device__ float g_f2[10000 * 512];
__device__ float g_part[20480000];               // split-K partials (82 MB)

// ---------------- helpers ----------------------------------------------------
__device__ __forceinline__ void split2(float x, __nv_bfloat16& h, __nv_bfloat16& l) {
    h = __float2bfloat16(x);
    l = __float2bfloat16(x - __bfloat162float(h));
}

__device__ __forceinline__ void cp16(uint32_t daddr, const void* src, int ok) {
    int sz = ok ? 16 : 0;
    asm volatile("cp.async.cg.shared.global [%0], [%1], 16, %2;"
                 :: "r"(daddr), "l"(src), "r"(sz));
}
__device__ __forceinline__ void cp_commit() {
    asm volatile("cp.async.commit_group;");
}
__device__ __forceinline__ void cp_wait1() {
    asm volatile("cp.async.wait_group 1;");
}
__device__ __forceinline__ void ldsm4(uint32_t& r0, uint32_t& r1, uint32_t& r2,
                                      uint32_t& r3, uint32_t addr) {
    asm volatile("ldmatrix.sync.aligned.m8n8.x4.shared.b16 {%0,%1,%2,%3}, [%4];"
                 : "=r"(r0), "=r"(r1), "=r"(r2), "=r"(r3) : "r"(addr));
}
__device__ __forceinline__ void mma16816(float c[4], const uint32_t a[4],
                                         const uint32_t b[2]) {
    asm volatile(
        "mma.sync.aligned.m16n8k16.row.col.f32.bf16.bf16.f32 "
        "{%0,%1,%2,%3}, {%4,%5,%6,%7}, {%8,%9}, {%0,%1,%2,%3};"
        : "+f"(c[0]), "+f"(c[1]), "+f"(c[2]), "+f"(c[3])
        : "r"(a[0]), "r"(a[1]), "r"(a[2]), "r"(a[3]), "r"(b[0]), "r"(b[1]));
}

// ---------------- adj -> bf16 (hi only), float4 -----------------------------
__global__ void conv_vec4(const float* __restrict__ x,
                          __nv_bfloat16* __restrict__ hi, int n4)
{
    int i = blockIdx.x * blockDim.x + threadIdx.x;
    if (i >= n4) return;
    float4 v = reinterpret_cast<const float4*>(x)[i];
    reinterpret_cast<__nv_bfloat162*>(hi)[2 * i + 0] =
        __halves2bfloat162(__float2bfloat16(v.x), __float2bfloat16(v.y));
    reinterpret_cast<__nv_bfloat162*>(hi)[2 * i + 1] =
        __halves2bfloat162(__float2bfloat16(v.z), __float2bfloat16(v.w));
}

// ---------------- split-K partial reduce + activation (+optional split) -----
template <int ACT, int S, int WSP>
__global__ void reduce_act(const float* __restrict__ in, long long stride,
                           float* __restrict__ out, int n4,
                           __nv_bfloat16* __restrict__ hi,
                           __nv_bfloat16* __restrict__ lo,
                           int ncols, int lds)
{
    int i = blockIdx.x * blockDim.x + threadIdx.x;
    if (i >= n4) return;
    float4 a = reinterpret_cast<const float4*>(in)[i];
    #pragma unroll
    for (int p = 1; p < S; p++) {
        float4 b = reinterpret_cast<const float4*>(in + (long long)p * stride)[i];
        a.x += b.x; a.y += b.y; a.z += b.z; a.w += b.w;
    }
    if (ACT == 1) {
        a.x = tanhf(a.x); a.y = tanhf(a.y); a.z = tanhf(a.z); a.w = tanhf(a.w);
    }
    reinterpret_cast<float4*>(out)[i] = a;
    if (WSP) {
        int e   = i * 4;
        int row = e / ncols;
        int col = e - row * ncols;       // ncols % 4 == 0 -> quad in one row
        float v[4] = {a.x, a.y, a.z, a.w};
        #pragma unroll
        for (int q = 0; q < 4; q++) {
            __nv_bfloat16 h, l;
            split2(v[q], h, l);
            hi[(size_t)row * lds + col + q] = h;
            lo[(size_t)row * lds + col + q] = l;
        }
    }
}

// ---------------- transpose + split: T[Kt,Nn] fp32 -> hi/lo [Nn,Kt] bf16 ----
__global__ void tsplit_kernel(const float* __restrict__ T, int Kt, int Nn,
                              __nv_bfloat16* __restrict__ hi,
                              __nv_bfloat16* __restrict__ lo)
{
    __shared__ float sm[32][33];
    int tx = threadIdx.x & 31;
    int ty = threadIdx.x >> 5;
    int k0 = blockIdx.y * 32;
    int n0 = blockIdx.x * 32;
    #pragma unroll
    for (int r = 0; r < 4; r++) {
        int row = k0 + ty + r * 8;
        int col = n0 + tx;
        sm[ty + r * 8][tx] = (row < Kt && col < Nn) ? T[(size_t)row * Nn + col] : 0.0f;
    }
    __syncthreads();
    #pragma unroll
    for (int r = 0; r < 4; r++) {
        int n = n0 + ty + r * 8;
        int k = k0 + tx;
        if (n < Nn && k < Kt) {
            float v = sm[tx][ty + r * 8];
            __nv_bfloat16 h, l;
            split2(v, h, l);
            hi[(size_t)n * Kt + k] = h;
            lo[(size_t)n * Kt + k] = l;
        }
    }
}

// ---------------- unified 2-term tensor-core GEMM ---------------------------
// C[M,N] = A[M,K] @ (BH[N,K] + BL[N,K])^T.  ACT: 0 none, 2 sigmoid.
// MIRROR: triangular grid + symmetric mirror store (M == N, A/B from same z).
// kseg > 0: split-K; blockIdx.z segment; partial -> C + z*M*ldc (no act).
template <int ACT, int MIRROR>
__global__ __launch_bounds__(256, 2) void mma_gemm(
    const __nv_bfloat16* __restrict__ A, int lda,
    const __nv_bfloat16* __restrict__ Bhi, const __nv_bfloat16* __restrict__ Blo, int ldb,
    float* __restrict__ C, int ldc,
    int M, int N, int K, int kseg)
{
    extern __shared__ char smem[];
    constexpr int STAGE = 3 * ARR_BYTES;

    const int t    = threadIdx.x;
    const int lane = t & 31;
    const int wid  = t >> 5;
    const int wm   = (wid >> 2) * 64;
    const int wn   = (wid & 3) * 32;
    const int g    = lane >> 2;
    const int tg   = lane & 3;

    if (kseg > 0) {
        int kb = blockIdx.z * kseg;
        A   += kb;
        Bhi += kb;
        Blo += kb;
        C += (size_t)blockIdx.z * M * ldc;
        K = min(K - kb, kseg);
    }

    int bx, by;
    if (MIRROR) {
        int bid = blockIdx.x;
        by = (int)((sqrtf(8.0f * (float)bid + 1.0f) - 1.0f) * 0.5f);
        while ((by + 1) * (by + 2) / 2 <= bid) by++;
        while (by * (by + 1) / 2 > bid) by--;
        bx = bid - by * (by + 1) / 2;
    } else {
        bx = blockIdx.x;
        by = blockIdx.y;
    }
    const int m0 = by * 128;
    const int n0 = bx * 128;

    float acc[4][4][4];
    #pragma unroll
    for (int i = 0; i < 4; i++)
        #pragma unroll
        for (int j = 0; j < 4; j++)
            #pragma unroll
            for (int c = 0; c < 4; c++) acc[i][j][c] = 0.0f;

    const int a_row = lane & 15;
    const int a_c8  = (lane >> 4) * 8;
    const int b_row = (lane & 7) + ((lane >> 4) << 3);
    const int b_c8  = ((lane >> 3) & 1) * 8;

    const int ntiles = (K + 31) / 32;

    auto load_stage = [&](int s, int k0) {
        uint32_t base = (uint32_t)__cvta_generic_to_shared(smem) + s * STAGE;
        #pragma unroll
        for (int it = 0; it < 6; it++) {
            int idx = t + it * 256;
            int arr = idx >> 9;             // 0:A 1:BH 2:BL
            int rem = idx & 511;
            int r   = rem >> 2;
            int c8  = (rem & 3) * 8;
            int gk  = k0 + c8;
            int kok = (gk < K);
            const __nv_bfloat16* src;
            int ok;
            if (arr == 0) {
                int ga = m0 + r;
                ok  = kok && (ga < M);
                src = A + (ok ? ((size_t)ga * lda + gk) : 0);
            } else {
                int gb = n0 + r;
                ok  = kok && (gb < N);
                src = (arr == 1 ? Bhi : Blo) + (ok ? ((size_t)gb * ldb + gk) : 0);
            }
            uint32_t so = (uint32_t)(r * SSTR + c8) * 2;
            cp16(base + (uint32_t)arr * ARR_BYTES + so, src, ok);
        }
    };

    load_stage(0, 0);
    cp_commit();

    int s = 0;
    for (int kt = 0; kt < ntiles; kt++) {
        __syncthreads();
        load_stage(s ^ 1, (kt + 1) * 32);
        cp_commit();
        cp_wait1();
        __syncthreads();

        const char* sb = smem + s * STAGE;
        const __nv_bfloat16* sA  = (const __nv_bfloat16*)(sb);
        const __nv_bfloat16* sBH = (const __nv_bfloat16*)(sb + 1 * ARR_BYTES);
        const __nv_bfloat16* sBL = (const __nv_bfloat16*)(sb + 2 * ARR_BYTES);

        #pragma unroll
        for (int ks = 0; ks < 32; ks += 16) {
            uint32_t ah[4][4], bh[2][4], bl[2][4];
            #pragma unroll
            for (int i = 0; i < 4; i++) {
                int off = (wm + i * 16 + a_row) * SSTR + ks + a_c8;
                ldsm4(ah[i][0], ah[i][1], ah[i][2], ah[i][3],
                      (uint32_t)__cvta_generic_to_shared(sA + off));
            }
            #pragma unroll
            for (int jp = 0; jp < 2; jp++) {
                int off = (wn + jp * 16 + b_row) * SSTR + ks + b_c8;
                ldsm4(bh[jp][0], bh[jp][1], bh[jp][2], bh[jp][3],
                      (uint32_t)__cvta_generic_to_shared(sBH + off));
                ldsm4(bl[jp][0], bl[jp][1], bl[jp][2], bl[jp][3],
                      (uint32_t)__cvta_generic_to_shared(sBL + off));
            }
            #pragma unroll
            for (int i = 0; i < 4; i++)
                #pragma unroll
                for (int j = 0; j < 4; j++)
                    mma16816(acc[i][j], ah[i], &bh[j >> 1][(j & 1) * 2]);
            #pragma unroll
            for (int i = 0; i < 4; i++)
                #pragma unroll
                for (int j = 0; j < 4; j++)
                    mma16816(acc[i][j], ah[i], &bl[j >> 1][(j & 1) * 2]);
        }
        s ^= 1;
    }

    const bool do_mirror = MIRROR && (bx != by);
    float* tile = (float*)smem;       // 128 x 132 fp32 (syrk smem = 67584)
    if (do_mirror) __syncthreads();

    #pragma unroll
    for (int i = 0; i < 4; i++) {
        #pragma unroll
        for (int j = 0; j < 4; j++) {
            int nl = wn + j * 8 + 2 * tg;
            int cn = n0 + nl;
            if (cn >= N) continue;
            #pragma unroll
            for (int h = 0; h < 2; h++) {
                int ml = wm + i * 16 + g + h * 8;
                int rm = m0 + ml;
                if (rm >= M) continue;
                float v0 = acc[i][j][2 * h + 0];
                float v1 = acc[i][j][2 * h + 1];
                if (ACT == 2) {
                    v0 = 1.0f / (1.0f + expf(-v0));
                    v1 = 1.0f / (1.0f + expf(-v1));
                }
                C[(size_t)rm * ldc + cn]     = v0;
                C[(size_t)rm * ldc + cn + 1] = v1;
                if (do_mirror) {
                    tile[(nl + 0) * 132 + ml] = v0;
                    tile[(nl + 1) * 132 + ml] = v1;
                }
            }
        }
    }

    if (do_mirror) {
        __syncthreads();
        for (int i = t; i < 128 * 32; i += 256) {
            int r  = i >> 5;
            int c4 = (i & 31) * 4;
            int gr = n0 + r;
            int gc = m0 + c4;
            if (gr < N && gc < M) {
                float4 v = *reinterpret_cast<const float4*>(&tile[r * 132 + c4]);
                *reinterpret_cast<float4*>(&C[(size_t)gr * ldc + gc]) = v;
            }
        }
    }
}

// ---------------- small fp32 SIMT GEMM (NN, no act) for X @ W ---------------
#define BM 128
#define BN 128
#define BK 8
__global__ __launch_bounds__(256) void simt_gemm(
    const float* __restrict__ A, const float* __restrict__ B,
    float* __restrict__ C, int M, int N, int K)
{
    __shared__ float As[BK][BM];
    __shared__ float Bs[BK][BN];
    const int t  = threadIdx.x;
    const int m0 = blockIdx.y * BM;
    const int n0 = blockIdx.x * BN;
    const int ar = t >> 1, ac = (t & 1) * 4;
    const int br = t >> 5, bc = (t & 31) * 4;
    const int ty = t >> 4, tx = t & 15;

    float acc[8][8];
    #pragma unroll
    for (int i = 0; i < 8; i++)
        #pragma unroll
        for (int j = 0; j < 8; j++) acc[i][j] = 0.0f;

    for (int k0 = 0; k0 < K; k0 += BK) {
        float4 av = make_float4(0.f, 0.f, 0.f, 0.f);
        if (m0 + ar < M && k0 + ac < K)
            av = *reinterpret_cast<const float4*>(A + (size_t)(m0 + ar) * K + k0 + ac);
        As[ac + 0][ar] = av.x; As[ac + 1][ar] = av.y;
        As[ac + 2][ar] = av.z; As[ac + 3][ar] = av.w;
        float4 bv = make_float4(0.f, 0.f, 0.f, 0.f);
        if (k0 + br < K && n0 + bc < N)
            bv = *reinterpret_cast<const float4*>(B + (size_t)(k0 + br) * N + n0 + bc);
        *reinterpret_cast<float4*>(&Bs[br][bc]) = bv;
        __syncthreads();
        #pragma unroll
        for (int kk = 0; kk < BK; kk++) {
            float a[8], b[8];
            *reinterpret_cast<float4*>(&a[0]) = *reinterpret_cast<const float4*>(&As[kk][ty * 8]);
            *reinterpret_cast<float4*>(&a[4]) = *reinterpret_cast<const float4*>(&As[kk][ty * 8 + 4]);
            *reinterpret_cast<float4*>(&b[0]) = *reinterpret_cast<const float4*>(&Bs[kk][tx * 8]);
            *reinterpret_cast<float4*>(&b[4]) = *reinterpret_cast<const float4*>(&Bs[kk][tx * 8 + 4]);
            #pragma unroll
            for (int i = 0; i < 8; i++)
                #pragma unroll
                for (int j = 0; j < 8; j++)
                    acc[i][j] = fmaf(a[i], b[j], acc[i][j]);
        }
        __syncthreads();
    }
    #pragma unroll
    for (int i = 0; i < 8; i++) {
        int m = m0 + ty * 8 + i;
        if (m >= M) continue;
        #pragma unroll
        for (int j = 0; j < 8; j++) {
            int n = n0 + tx * 8 + j;
            if (n < N) C[(size_t)m * N + n] = acc[i][j];
        }
    }
}

// ---------------- driver -----------------------------------------------------
extern "C" void kernel_launch(void* const* d_in, const int* in_sizes, int n_in,
                              void* d_out, int out_size)
{
    const float* z_igae = (const float*)d_in[0];  // [10000, 20]
    const float* adj    = (const float*)d_in[1];  // [10000, 10000]
    const float* w3     = (const float*)d_in[2];  // [20, 256]
    const float* w4     = (const float*)d_in[3];  // [256, 128]
    const float* w5     = (const float*)d_in[4];  // [128, 500]

    float* out      = (float*)d_out;
    float* z_hat    = out;                          // [10000, 500]
    float* z_hatadj = out + (size_t)NROWS * 500;    // [10000, 10000]

    __nv_bfloat16 *adjH, *btH, *btL, *zhH, *zhL;
    float *f1, *f2, *part;
    cudaGetSymbolAddress((void**)&adjH, g_adj_hi);
    cudaGetSymbolAddress((void**)&btH,  g_bt_hi);
    cudaGetSymbolAddress((void**)&btL,  g_bt_lo);
    cudaGetSymbolAddress((void**)&zhH,  g_zh_hi);
    cudaGetSymbolAddress((void**)&zhL,  g_zh_lo);
    cudaGetSymbolAddress((void**)&f1,   g_f1);
    cudaGetSymbolAddress((void**)&f2,   g_f2);
    cudaGetSymbolAddress((void**)&part, g_part);

    cudaFuncSetAttribute(mma_gemm<0, 0>,
                         cudaFuncAttributeMaxDynamicSharedMemorySize, SMEM_G);
    cudaFuncSetAttribute(mma_gemm<2, 1>,
                         cudaFuncAttributeMaxDynamicSharedMemorySize, SMEM_MIR);

    // 0. adj -> bf16 (hi only)
    {
        int n4 = (int)(ADJ_N / 4);
        conv_vec4<<<(n4 + 255) / 256, 256>>>(adj, adjH, n4);
    }

    dim3 blk(256);

    // 1. T1 = z_igae @ w3  [10000,256]
    simt_gemm<<<dim3(2, 79), blk>>>(z_igae, w3, f1, NROWS, 256, 20);
    // 2. transpose+split T1 -> [256,10000]
    tsplit_kernel<<<dim3(8, 313), blk>>>(f1, NROWS, 256, btH, btL);
    // 3. Z1 = tanh(adj @ T1): split-K=8 (1264 CTAs, 5 waves), reduce+tanh
    mma_gemm<0, 0><<<dim3(2, 79, 8), blk, SMEM_G>>>(
        adjH, NROWS, btH, btL, NROWS, part, 256, NROWS, 256, NROWS, 1256);
    {
        int n4 = NROWS * 256 / 4;
        reduce_act<1, 8, 0><<<(n4 + 255) / 256, blk>>>(
            part, (long long)NROWS * 256, f2, n4, nullptr, nullptr, 0, 0);
    }
    // 4. T2 = Z1 @ w4  [10000,128]
    simt_gemm<<<dim3(1, 79), blk>>>(f2, w4, f1, NROWS, 128, 256);
    // 5. transpose+split T2 -> [128,10000]
    tsplit_kernel<<<dim3(4, 313), blk>>>(f1, NROWS, 128, btH, btL);
    // 6. Z2 = tanh(adj @ T2): split-K=16 (1264 CTAs, 5 waves), reduce+tanh
    mma_gemm<0, 0><<<dim3(1, 79, 16), blk, SMEM_G>>>(
        adjH, NROWS, btH, btL, NROWS, part, 128, NROWS, 128, NROWS, 632);
    {
        int n4 = NROWS * 128 / 4;
        reduce_act<1, 16, 0><<<(n4 + 255) / 256, blk>>>(
            part, (long long)NROWS * 128, f2, n4, nullptr, nullptr, 0, 0);
    }
    // 7. T3 = Z2 @ w5  [10000,500]
    simt_gemm<<<dim3(4, 79), blk>>>(f2, w5, f1, NROWS, 500, 128);
    // 8. transpose+split T3 -> [500,10000]
    tsplit_kernel<<<dim3(16, 313), blk>>>(f1, NROWS, 500, btH, btL);
    // 9. z_hat = adj @ T3: split-K=4 (1264 CTAs, 5 waves); reduce emits
    //    z_hat + bf16 split (lds=512; pad cols stay 0 from static zero-init)
    mma_gemm<0, 0><<<dim3(4, 79, 4), blk, SMEM_G>>>(
        adjH, NROWS, btH, btL, NROWS, part, 500, NROWS, 500, NROWS, 2504);
    {
        int n4 = NROWS * 500 / 4;
        reduce_act<0, 4, 1><<<(n4 + 255) / 256, blk>>>(
            part, (long long)NROWS * 500, z_hat, n4, zhH, zhL, 500, 512);
    }
    // 10. z_hat_adj = sigmoid(z_hat @ z_hat^T): 2-term (A = zhH, B = zhH+zhL),
    //     triangular grid + mirror; smem sized for the 128x132 mirror tile.
    {
        int nblk = 79 * 80 / 2;  // 3160
        mma_gemm<2, 1><<<dim3(nblk), blk, SMEM_MIR>>>(
            zhH, 512, zhH, zhL, 512, z_hatadj, NROWS, NROWS, NROWS, 512, 0);
    }
}